// round 1
// baseline (speedup 1.0000x reference)
#include <cuda_runtime.h>
#include <math.h>

#define NB   4
#define CH   256
#define GRP  4
#define CG   64
#define KP   9
#define OMC  108
#define GNG  16
#define CPG  16   // channels per GN group

// ---------------- scratch (static device globals; no runtime alloc) ------------
__device__ float g_x0[NB*80*80*CH];     // x0 NHWC
__device__ float g_x1[NB*40*40*CH];     // x1 NHWC
__device__ float g_x2[NB*20*20*CH];     // x2 NHWC
__device__ float g_dw[NB*80*80*CH];     // dw_conv output NHWC (max res)
__device__ float g_om[NB*80*80*OMC];    // offset/mask conv output NHWC
__device__ float g_feat[NB*80*80*CH];   // sampled + GN'd feature NHWC
__device__ float g_up[NB*80*80*CH];     // upsampled feature NHWC
__device__ float g_sum[NB*80*80*CH];    // per-level accumulated sum NHWC
__device__ float g_wT[576*OMC];         // transposed offset conv weights
__device__ float g_a[NB];               // scale_attn per-sample scalar
__device__ float g_y[NB*CH];            // dyrelu pooled means
__device__ float g_hbuf[NB*64];         // dyrelu hidden
__device__ float g_z[NB*1024];          // dyrelu coefficients (a1,b1,a2,b2)

__device__ __forceinline__ const float* pick_x(int s){
    return s==0 ? g_x0 : (s==1 ? g_x1 : g_x2);
}
__device__ __forceinline__ float* pick_xm(int s){
    return s==0 ? g_x0 : (s==1 ? g_x1 : g_x2);
}

// ---------------- kernels -------------------------------------------------------

// NCHW (input) -> NHWC (scratch)
__global__ void k_tr(const float* __restrict__ in, int sel, int H, int W){
    float* out = pick_xm(sel);
    int total = NB*CH*H*W;
    for (int i = blockIdx.x*blockDim.x + threadIdx.x; i < total; i += gridDim.x*blockDim.x){
        int w = i % W;
        int h = (i / W) % H;
        int c = (i / (W*H)) % CH;
        int n = i / (W*H*CH);
        out[((n*H + h)*W + w)*CH + c] = in[i];
    }
}

// transpose offset conv weights: wT[(ic*9+tap)*108 + oc] = off_w[oc*576 + ic*9+tap]
__global__ void k_wt(const float* __restrict__ ow){
    int i = blockIdx.x*blockDim.x + threadIdx.x;
    if (i < 576*OMC){
        int ii = i / OMC, oc = i % OMC;
        g_wT[i] = ow[oc*576 + ii];
    }
}

// depthwise 3x3 conv + scale/bias + SiLU, NHWC
__global__ void k_dw(int sel, int H, int W,
                     const float* __restrict__ wgt,
                     const float* __restrict__ sc,
                     const float* __restrict__ bi){
    const float* x = pick_x(sel);
    int total = NB*H*W*CH;
    for (int i = blockIdx.x*blockDim.x + threadIdx.x; i < total; i += gridDim.x*blockDim.x){
        int c  = i & 255;
        int hw = i >> 8;
        int w  = hw % W;
        int h  = (hw / W) % H;
        int n  = hw / (W*H);
        float acc = 0.f;
        #pragma unroll
        for (int dy = 0; dy < 3; ++dy){
            int yy = h + dy - 1;
            if (yy < 0 || yy >= H) continue;
            #pragma unroll
            for (int dx = 0; dx < 3; ++dx){
                int xx = w + dx - 1;
                if (xx < 0 || xx >= W) continue;
                acc += x[((n*H + yy)*W + xx)*CH + c] * wgt[c*9 + dy*3 + dx];
            }
        }
        float yv = acc*sc[c] + bi[c];
        g_dw[i] = yv / (1.f + expf(-yv));
    }
}

// grouped conv 256->108, 3x3, groups=4, NHWC.
// block: one (n,h,w0..w0+7) row tile. 216 active threads = 108 oc x 2 pixel-halves,
// each thread computes 4 pixels (register tiling to amortize weight loads).
__global__ void k_om(int H, int W, const float* __restrict__ ob){
    __shared__ float sp[3*10*CH];   // 30720 B
    int ntiles = (W + 7) / 8;
    int b    = blockIdx.x;
    int tile = b % ntiles;
    int h    = (b / ntiles) % H;
    int n    = b / (ntiles*H);
    int w0   = tile * 8;

    for (int i = threadIdx.x; i < 3*10*CH; i += blockDim.x){
        int dy = i / (10*CH);
        int r  = i % (10*CH);
        int wl = r / CH;
        int ic = r % CH;
        int yy = h + dy - 1;
        int xx = w0 + wl - 1;
        sp[i] = (yy >= 0 && yy < H && xx >= 0 && xx < W)
                ? g_dw[((n*H + yy)*W + xx)*CH + ic] : 0.f;
    }
    __syncthreads();

    int t = threadIdx.x;
    if (t < 216){
        int oc   = t % OMC;
        int half = t / OMC;
        int g    = oc / 27;
        int cb   = g * CG;
        int p0   = half * 4;
        float a0 = 0.f, a1 = 0.f, a2 = 0.f, a3 = 0.f;
        const float* wp = g_wT + oc;
        for (int ic = 0; ic < CG; ++ic){
            int cc = cb + ic;
            #pragma unroll
            for (int tp = 0; tp < 9; ++tp){
                float wv = wp[(ic*9 + tp)*OMC];
                int dy = tp / 3, dx = tp % 3;
                const float* srow = sp + (dy*10 + dx + p0)*CH + cc;
                a0 += srow[0*CH] * wv;
                a1 += srow[1*CH] * wv;
                a2 += srow[2*CH] * wv;
                a3 += srow[3*CH] * wv;
            }
        }
        float bb = ob[oc];
        float accs[4] = {a0, a1, a2, a3};
        #pragma unroll
        for (int p = 0; p < 4; ++p){
            int ww = w0 + p0 + p;
            if (ww < W) g_om[((n*H + h)*W + ww)*OMC + oc] = accs[p] + bb;
        }
    }
}

// DCNv3 deformable sampling: block = one output pixel, thread = channel
__global__ void k_samp(int sel, int H, int W, int Ho, int Wo, int stride, int use_softmax){
    __shared__ float sm[OMC];
    __shared__ float smk[36];
    const float* x = pick_x(sel);
    int b  = blockIdx.x;
    int wo = b % Wo;
    int ho = (b / Wo) % Ho;
    int n  = b / (Wo*Ho);
    int hs = ho * stride, ws = wo * stride;
    int t  = threadIdx.x;

    if (t < OMC) sm[t] = g_om[((n*H + hs)*W + ws)*OMC + t];
    __syncthreads();

    if (use_softmax){
        if (t < 4){
            float mx = -1e30f;
            #pragma unroll
            for (int k = 0; k < 9; ++k) mx = fmaxf(mx, sm[72 + t*9 + k]);
            float e[9], s = 0.f;
            #pragma unroll
            for (int k = 0; k < 9; ++k){ e[k] = expf(sm[72 + t*9 + k] - mx); s += e[k]; }
            float inv = 1.f / s;
            #pragma unroll
            for (int k = 0; k < 9; ++k) smk[t*9 + k] = e[k]*inv;
        }
    } else {
        if (t < 36) smk[t] = 1.f / (1.f + expf(-sm[72 + t]));
    }
    __syncthreads();

    int c = t, g = c >> 6;
    float by = (float)(ho*stride), bx = (float)(wo*stride);
    float acc = 0.f;
    #pragma unroll
    for (int k = 0; k < 9; ++k){
        float py = by + (float)(k/3 - 1) + sm[g*18 + k*2 + 0];
        float px = bx + (float)(k%3 - 1) + sm[g*18 + k*2 + 1];
        float msk = smk[g*9 + k];
        float fy = floorf(py), fx = floorf(px);
        float wy = py - fy, wx = px - fx;
        int iy = (int)fy, ix = (int)fx;
        #pragma unroll
        for (int dy = 0; dy < 2; ++dy){
            int yy = iy + dy;
            if (yy < 0 || yy >= H) continue;
            float wgy = dy ? wy : (1.f - wy);
            #pragma unroll
            for (int dx = 0; dx < 2; ++dx){
                int xx = ix + dx;
                if (xx < 0 || xx >= W) continue;
                float wgt = wgy * (dx ? wx : (1.f - wx)) * msk;
                acc += wgt * x[((n*H + yy)*W + xx)*CH + c];
            }
        }
    }
    g_feat[((n*Ho + ho)*Wo + wo)*CH + c] = acc;
}

// group norm, in-place on g_feat. block = (n, gn group)
__global__ void k_gn(int Ho, int Wo,
                     const float* __restrict__ gam,
                     const float* __restrict__ bet){
    __shared__ double rs[256], rss[256];
    __shared__ float smu, sinv;
    int n   = blockIdx.x / GNG;
    int grp = blockIdx.x % GNG;
    int HW  = Ho*Wo;
    int cnt = HW*CPG;
    double s = 0.0, ss = 0.0;
    for (int i = threadIdx.x; i < cnt; i += blockDim.x){
        int hw = i / CPG, cc = i % CPG;
        float v = g_feat[(n*HW + hw)*CH + grp*CPG + cc];
        s += v; ss += (double)v*v;
    }
    rs[threadIdx.x] = s; rss[threadIdx.x] = ss;
    __syncthreads();
    for (int o = 128; o > 0; o >>= 1){
        if (threadIdx.x < o){
            rs[threadIdx.x]  += rs[threadIdx.x + o];
            rss[threadIdx.x] += rss[threadIdx.x + o];
        }
        __syncthreads();
    }
    if (threadIdx.x == 0){
        double mu  = rs[0] / cnt;
        double var = rss[0] / cnt - mu*mu;
        smu  = (float)mu;
        sinv = (float)(1.0 / sqrt(var + 1e-5));
    }
    __syncthreads();
    float mu = smu, inv = sinv;
    for (int i = threadIdx.x; i < cnt; i += blockDim.x){
        int hw = i / CPG, cc = i % CPG;
        int c   = grp*CPG + cc;
        int idx = (n*HW + hw)*CH + c;
        g_feat[idx] = (g_feat[idx] - mu)*inv*gam[c] + bet[c];
    }
}

// align-corners bilinear upsample g_feat (Hs,Ws) -> g_up (Ho,Wo), NHWC
__global__ void k_up(int Hs, int Ws, int Ho, int Wo){
    int total = NB*Ho*Wo*CH;
    float sy = (Ho > 1) ? (float)(Hs - 1)/(float)(Ho - 1) : 0.f;
    float sx = (Wo > 1) ? (float)(Ws - 1)/(float)(Wo - 1) : 0.f;
    for (int i = blockIdx.x*blockDim.x + threadIdx.x; i < total; i += gridDim.x*blockDim.x){
        int c  = i & 255;
        int hw = i >> 8;
        int w  = hw % Wo;
        int h  = (hw / Wo) % Ho;
        int n  = hw / (Wo*Ho);
        float cy = h*sy, cx = w*sx;
        int y0 = (int)floorf(cy), x0 = (int)floorf(cx);
        int y1 = min(y0 + 1, Hs - 1), x1 = min(x0 + 1, Ws - 1);
        float wy = cy - (float)y0, wx = cx - (float)x0;
        const float* f = g_feat;
        float v00 = f[((n*Hs + y0)*Ws + x0)*CH + c];
        float v01 = f[((n*Hs + y0)*Ws + x1)*CH + c];
        float v10 = f[((n*Hs + y1)*Ws + x0)*CH + c];
        float v11 = f[((n*Hs + y1)*Ws + x1)*CH + c];
        float t0 = v00*(1.f - wy) + v10*wy;
        float t1 = v01*(1.f - wy) + v11*wy;
        g_up[i] = t0*(1.f - wx) + t1*wx;
    }
}

// scale_attn scalar: a_n = clip((relu(sum_chw f*w_c / HW + b)+3)/6, 0, 1)
__global__ void k_attn(int use_up, int Ho, int Wo,
                       const float* __restrict__ saw,
                       const float* __restrict__ sab){
    __shared__ double red[256];
    const float* f = use_up ? g_up : g_feat;
    int n  = blockIdx.x;
    int HW = Ho*Wo;
    int tot4 = HW*CH/4;
    const float4* f4 = (const float4*)(f + (size_t)n*HW*CH);
    double s = 0.0;
    for (int i = threadIdx.x; i < tot4; i += blockDim.x){
        float4 v = f4[i];
        int c = (i*4) & 255;
        s += (double)v.x*saw[c] + (double)v.y*saw[c+1]
           + (double)v.z*saw[c+2] + (double)v.w*saw[c+3];
    }
    red[threadIdx.x] = s;
    __syncthreads();
    for (int o = 128; o > 0; o >>= 1){
        if (threadIdx.x < o) red[threadIdx.x] += red[threadIdx.x + o];
        __syncthreads();
    }
    if (threadIdx.x == 0){
        float a = (float)(red[0] / HW) + sab[0];
        a = fmaxf(a, 0.f);
        a = fminf(fmaxf((a + 3.f)/6.f, 0.f), 1.f);
        g_a[n] = a;
    }
}

// sum accumulate: g_sum (=|+=) feat * a_n
__global__ void k_acc(int use_up, int first, int Ho, int Wo){
    const float* f = use_up ? g_up : g_feat;
    int total = NB*Ho*Wo*CH;
    int per   = Ho*Wo*CH;
    for (int i = blockIdx.x*blockDim.x + threadIdx.x; i < total; i += gridDim.x*blockDim.x){
        int n = i / per;
        float v = f[i] * g_a[n];
        g_sum[i] = first ? v : (g_sum[i] + v);
    }
}

__global__ void k_yzero(){
    int i = blockIdx.x*blockDim.x + threadIdx.x;
    if (i < NB*CH) g_y[i] = 0.f;
}

// per-channel mean of (sum/n_lvls): grid (NB,16), thread = channel
__global__ void k_ymean(int Ho, int Wo, float invscale){
    int n = blockIdx.x, chunk = blockIdx.y;
    int HW = Ho*Wo;
    int per = HW / 16;
    int c = threadIdx.x;
    float s = 0.f;
    int hw0 = chunk*per;
    for (int hw = hw0; hw < hw0 + per; ++hw) s += g_sum[(n*HW + hw)*CH + c];
    atomicAdd(&g_y[n*CH + c], s*invscale);
}

__global__ void k_fc1(const float* __restrict__ w1, const float* __restrict__ b1){
    int t = threadIdx.x;     // 256 threads = (n, j)
    int n = t / 64, j = t % 64;
    float s = b1[j];
    for (int c = 0; c < CH; ++c) s += g_y[n*CH + c]*w1[j*CH + c];
    g_hbuf[n*64 + j] = fmaxf(s, 0.f);
}

__global__ void k_fc2(const float* __restrict__ w2, const float* __restrict__ b2){
    int og = blockIdx.x*blockDim.x + threadIdx.x;
    if (og >= NB*1024) return;
    int n = og / 1024, o = og % 1024;
    float s = b2[o];
    #pragma unroll
    for (int j = 0; j < 64; ++j) s += g_hbuf[n*64 + j]*w2[o*64 + j];
    float z = fminf(fmaxf(s + 3.f, 0.f), 6.f)*(1.f/6.f);
    int q = o / 256;
    float v;
    if      (q == 0) v = (z - 0.5f)*2.f + 1.f;
    else if (q == 2) v = (z - 0.5f)*2.f;
    else             v = z - 0.5f;
    g_z[og] = v;
}

// dyrelu elementwise + NHWC->NCHW output write
__global__ void k_out(int Ho, int Wo, float invl, float* __restrict__ out){
    int total = NB*CH*Ho*Wo;
    int HW = Ho*Wo;
    for (int i = blockIdx.x*blockDim.x + threadIdx.x; i < total; i += gridDim.x*blockDim.x){
        int w = i % Wo;
        int h = (i / Wo) % Ho;
        int c = (i / HW) % CH;
        int n = i / (HW*CH);
        float f  = g_sum[((n*Ho + h)*Wo + w)*CH + c]*invl;
        float a1 = g_z[n*1024 + c];
        float b1 = g_z[n*1024 + 256 + c];
        float a2 = g_z[n*1024 + 512 + c];
        float b2 = g_z[n*1024 + 768 + c];
        out[i] = fmaxf(f*a1 + b1, f*a2 + b2);
    }
}

// ---------------- host ----------------------------------------------------------

static inline int gsz(int total){ return (total + 255) / 256; }

extern "C" void kernel_launch(void* const* d_in, const int* in_sizes, int n_in,
                              void* d_out, int out_size){
    const float* x0    = (const float*)d_in[0];
    const float* x1    = (const float*)d_in[1];
    const float* x2    = (const float*)d_in[2];
    const float* dw_w_h = (const float*)d_in[3];
    const float* dw_s_h = (const float*)d_in[4];
    const float* dw_b_h = (const float*)d_in[5];
    const float* dw_w_m = (const float*)d_in[6];
    const float* dw_s_m = (const float*)d_in[7];
    const float* dw_b_m = (const float*)d_in[8];
    const float* dw_w_l = (const float*)d_in[9];
    const float* dw_s_l = (const float*)d_in[10];
    const float* dw_b_l = (const float*)d_in[11];
    const float* off_w  = (const float*)d_in[12];
    const float* off_b  = (const float*)d_in[13];
    const float* gn_g_h = (const float*)d_in[14];
    const float* gn_b_h = (const float*)d_in[15];
    const float* gn_g_m = (const float*)d_in[16];
    const float* gn_b_m = (const float*)d_in[17];
    const float* gn_g_l = (const float*)d_in[18];
    const float* gn_b_l = (const float*)d_in[19];
    const float* sa_w   = (const float*)d_in[20];
    const float* sa_b   = (const float*)d_in[21];
    const float* fc1_w  = (const float*)d_in[22];
    const float* fc1_b  = (const float*)d_in[23];
    const float* fc2_w  = (const float*)d_in[24];
    const float* fc2_b  = (const float*)d_in[25];
    float* out = (float*)d_out;

    // input transposes + weight transpose
    k_tr<<<gsz(NB*CH*80*80), 256>>>(x0, 0, 80, 80);
    k_tr<<<gsz(NB*CH*40*40), 256>>>(x1, 1, 40, 40);
    k_tr<<<gsz(NB*CH*20*20), 256>>>(x2, 2, 20, 20);
    k_wt<<<gsz(576*OMC), 256>>>(off_w);

    // one branch: dw conv -> offset conv -> sample -> GN -> (upsample) -> attn -> accumulate
    auto branch = [&](int sel, int Hs, int Ws,
                      const float* dww, const float* dws, const float* dwb,
                      const float* gng, const float* gnb,
                      int softmax, int stride, int Ho, int Wo,
                      int upHo, int upWo, int first){
        k_dw<<<gsz(NB*Hs*Ws*CH), 256>>>(sel, Hs, Ws, dww, dws, dwb);
        int ntiles = (Ws + 7) / 8;
        k_om<<<NB*Hs*ntiles, 256>>>(Hs, Ws, off_b);
        k_samp<<<NB*Ho*Wo, 256>>>(sel, Hs, Ws, Ho, Wo, stride, softmax);
        k_gn<<<NB*GNG, 256>>>(Ho, Wo, gng, gnb);
        int use_up = 0, Hf = Ho, Wf = Wo;
        if (upHo){
            k_up<<<gsz(NB*upHo*upWo*CH), 256>>>(Ho, Wo, upHo, upWo);
            use_up = 1; Hf = upHo; Wf = upWo;
        }
        k_attn<<<NB, 256>>>(use_up, Hf, Wf, sa_w, sa_b);
        k_acc<<<gsz(NB*Hf*Wf*CH), 256>>>(use_up, first, Hf, Wf);
    };

    auto dyrelu = [&](int Ho, int Wo, int nlvls, float* optr){
        float inv = 1.f / (float)nlvls;
        k_yzero<<<gsz(NB*CH), 256>>>();
        k_ymean<<<dim3(NB, 16), 256>>>(Ho, Wo, 1.f/((float)(Ho*Wo)*(float)nlvls));
        k_fc1<<<1, 256>>>(fc1_w, fc1_b);
        k_fc2<<<gsz(NB*1024), 256>>>(fc2_w, fc2_b);
        k_out<<<gsz(NB*CH*Ho*Wo), 256>>>(Ho, Wo, inv, optr);
    };

    // ---------- level 0 (80x80): mid(x0) + high(x1 upsampled) ----------
    branch(0, 80, 80, dw_w_m, dw_s_m, dw_b_m, gn_g_m, gn_b_m, 0, 1, 80, 80, 0,  0,  1);
    branch(1, 40, 40, dw_w_h, dw_s_h, dw_b_h, gn_g_h, gn_b_h, 1, 1, 40, 40, 80, 80, 0);
    dyrelu(80, 80, 2, out);

    // ---------- level 1 (40x40): mid(x1) + low(x0,stride2) + high(x2 upsampled) ----------
    branch(1, 40, 40, dw_w_m, dw_s_m, dw_b_m, gn_g_m, gn_b_m, 0, 1, 40, 40, 0,  0,  1);
    branch(0, 80, 80, dw_w_l, dw_s_l, dw_b_l, gn_g_l, gn_b_l, 1, 2, 40, 40, 0,  0,  0);
    branch(2, 20, 20, dw_w_h, dw_s_h, dw_b_h, gn_g_h, gn_b_h, 1, 1, 20, 20, 40, 40, 0);
    dyrelu(40, 40, 3, out + NB*CH*80*80);

    // ---------- level 2 (20x20): mid(x2) + low(x1,stride2) ----------
    branch(2, 20, 20, dw_w_m, dw_s_m, dw_b_m, gn_g_m, gn_b_m, 0, 1, 20, 20, 0, 0, 1);
    branch(1, 40, 40, dw_w_l, dw_s_l, dw_b_l, gn_g_l, gn_b_l, 1, 2, 20, 20, 0, 0, 0);
    dyrelu(20, 20, 2, out + NB*CH*80*80 + NB*CH*40*40);
}

// round 2
// speedup vs baseline: 3.8238x; 3.8238x over previous
#include <cuda_runtime.h>
#include <math.h>

#define NB   4
#define CH   256
#define OMC  108

// ---------------- scratch ----------------
__device__ float g_x0[NB*80*80*CH];
__device__ float g_x1[NB*40*40*CH];
__device__ float g_x2[NB*20*20*CH];
__device__ float g_dw[NB*80*80*CH];
__device__ float g_om[NB*80*80*OMC];
__device__ float g_feat[NB*80*80*CH];   // raw sampled (pre-GN)
__device__ float g_sum[NB*80*80*CH];
__device__ float g_wT[576*OMC];
__device__ float g_a[NB];
__device__ float g_y[NB*CH];
__device__ float g_hbuf[NB*64];
__device__ float g_z[NB*1024];
__device__ float g_cmean[NB*CH];        // weighted per-channel spatial mean (raw)
__device__ float g_gmu[NB*16];          // GN group mean
__device__ float g_ginv[NB*16];         // GN group rsqrt(var+eps)

__device__ __forceinline__ const float* pick_x(int s){
    return s==0 ? g_x0 : (s==1 ? g_x1 : g_x2);
}
__device__ __forceinline__ float* pick_xm(int s){
    return s==0 ? g_x0 : (s==1 ? g_x1 : g_x2);
}

// ---------------- NCHW -> NHWC tiled transpose ----------------
__global__ void k_tr2(const float* __restrict__ in, int sel, int HW){
    __shared__ float tile[32][33];
    float* out = pick_xm(sel);
    int n  = blockIdx.z;
    int hw0 = blockIdx.x*32;
    int c0  = blockIdx.y*32;
    int tx = threadIdx.x, ty = threadIdx.y;  // (32,8)
    #pragma unroll
    for (int q = 0; q < 4; ++q){
        int c = c0 + ty + q*8;
        int hw = hw0 + tx;
        float v = (hw < HW) ? in[((size_t)n*CH + c)*HW + hw] : 0.f;
        tile[ty + q*8][tx] = v;
    }
    __syncthreads();
    #pragma unroll
    for (int q = 0; q < 4; ++q){
        int hw = hw0 + ty + q*8;
        int c  = c0 + tx;
        if (hw < HW) out[((size_t)n*HW + hw)*CH + c] = tile[tx][ty + q*8];
    }
}

// weight transpose
__global__ void k_wt(const float* __restrict__ ow){
    int i = blockIdx.x*blockDim.x + threadIdx.x;
    if (i < 576*OMC){
        int ii = i / OMC, oc = i % OMC;
        g_wT[i] = ow[oc*576 + ii];
    }
}

// depthwise 3x3 + scale/bias + SiLU
__global__ void k_dw(int sel, int H, int W,
                     const float* __restrict__ wgt,
                     const float* __restrict__ sc,
                     const float* __restrict__ bi){
    const float* x = pick_x(sel);
    int total = NB*H*W*CH;
    for (int i = blockIdx.x*blockDim.x + threadIdx.x; i < total; i += gridDim.x*blockDim.x){
        int c  = i & 255;
        int hw = i >> 8;
        int w  = hw % W;
        int h  = (hw / W) % H;
        int n  = hw / (W*H);
        float acc = 0.f;
        #pragma unroll
        for (int dy = 0; dy < 3; ++dy){
            int yy = h + dy - 1;
            if (yy < 0 || yy >= H) continue;
            #pragma unroll
            for (int dx = 0; dx < 3; ++dx){
                int xx = w + dx - 1;
                if (xx < 0 || xx >= W) continue;
                acc += x[((n*H + yy)*W + xx)*CH + c] * wgt[c*9 + dy*3 + dx];
            }
        }
        float yv = acc*sc[c] + bi[c];
        g_dw[i] = yv / (1.f + expf(-yv));
    }
}

// ---------------- grouped conv 256->108, register-tiled ----------------
// thread = (ocT in 0..35 -> 3 consecutive oc) x (pxq -> TPX pixels). per-tap
// weight slab staged in smem. strided variant computes only used pixels.
template<int STRIDE, int PXO, int TPX>
__global__ void __launch_bounds__(192, 2)
k_om2(int H, int W, int Ho, int Wo, const float* __restrict__ ob){
    constexpr int PWP = 24;
    constexpr int PW  = (PXO-1)*STRIDE + 3;
    constexpr int PXQ = PXO/TPX;
    static_assert(PW <= PWP, "patch width");
    extern __shared__ float sh[];
    float* patch = sh;                  // [3][CH][PWP]
    float* wslab = sh + 3*CH*PWP;       // [64][108]

    int ntiles = (Wo + PXO - 1)/PXO;
    int b    = blockIdx.x;
    int tile = b % ntiles;
    int ho   = (b / ntiles) % Ho;
    int n    = b / (ntiles*Ho);
    int wo0  = tile*PXO;
    int hsrc = ho*STRIDE;
    int wsrc0= wo0*STRIDE;

    for (int i = threadIdx.x; i < 3*PW*CH; i += blockDim.x){
        int c  = i & 255;
        int r  = i >> 8;
        int xx = r % PW;
        int dy = r / PW;
        int gy = hsrc + dy - 1, gx = wsrc0 + xx - 1;
        float v = 0.f;
        if (gy >= 0 && gy < H && gx >= 0 && gx < W)
            v = g_dw[((n*H + gy)*W + gx)*CH + c];
        patch[(dy*CH + c)*PWP + xx] = v;
    }

    int t   = threadIdx.x;
    int pxq = t % PXQ;
    int ocT = t / PXQ;
    bool act = ocT < 36;
    int oc0 = ocT*3;
    int cb  = (oc0/27)*64;

    float acc0[TPX], acc1[TPX], acc2[TPX];
    #pragma unroll
    for (int p = 0; p < TPX; ++p){ acc0[p]=0.f; acc1[p]=0.f; acc2[p]=0.f; }

    for (int tp = 0; tp < 9; ++tp){
        __syncthreads();
        for (int j = t; j < 64*108; j += blockDim.x){
            int oc = j % 108, ic = j / 108;
            wslab[j] = g_wT[(ic*9 + tp)*108 + oc];
        }
        __syncthreads();
        if (act){
            int dy = tp/3, dx = tp%3;
            const float* pr = patch + (dy*CH + cb)*PWP + pxq*TPX*STRIDE + dx;
            const float* wp = wslab + oc0;
            #pragma unroll 4
            for (int ic = 0; ic < 64; ++ic){
                float w0 = wp[0], w1 = wp[1], w2 = wp[2];
                #pragma unroll
                for (int p = 0; p < TPX; ++p){
                    float v = pr[p*STRIDE];
                    acc0[p] += v*w0; acc1[p] += v*w1; acc2[p] += v*w2;
                }
                wp += 108; pr += PWP;
            }
        }
    }
    if (act){
        float b0 = ob[oc0], b1 = ob[oc0+1], b2 = ob[oc0+2];
        #pragma unroll
        for (int p = 0; p < TPX; ++p){
            int wo = wo0 + pxq*TPX + p;
            if (wo < Wo){
                int base = ((n*Ho + ho)*Wo + wo)*OMC + oc0;
                g_om[base]   = acc0[p] + b0;
                g_om[base+1] = acc1[p] + b1;
                g_om[base+2] = acc2[p] + b2;
            }
        }
    }
}

// ---------------- DCNv3 sampler (writes RAW feature) ----------------
__global__ void k_samp(int sel, int H, int W, int Ho, int Wo, int stride, int use_softmax){
    __shared__ float sm[OMC];
    __shared__ float smk[36];
    const float* x = pick_x(sel);
    int b  = blockIdx.x;
    int wo = b % Wo;
    int ho = (b / Wo) % Ho;
    int n  = b / (Wo*Ho);
    int t  = threadIdx.x;

    if (t < OMC) sm[t] = g_om[((n*Ho + ho)*Wo + wo)*OMC + t];
    __syncthreads();

    if (use_softmax){
        if (t < 4){
            float mx = -1e30f;
            #pragma unroll
            for (int k = 0; k < 9; ++k) mx = fmaxf(mx, sm[72 + t*9 + k]);
            float e[9], s = 0.f;
            #pragma unroll
            for (int k = 0; k < 9; ++k){ e[k] = expf(sm[72 + t*9 + k] - mx); s += e[k]; }
            float inv = 1.f / s;
            #pragma unroll
            for (int k = 0; k < 9; ++k) smk[t*9 + k] = e[k]*inv;
        }
    } else {
        if (t < 36) smk[t] = 1.f / (1.f + expf(-sm[72 + t]));
    }
    __syncthreads();

    int c = t, g = c >> 6;
    float by = (float)(ho*stride), bx = (float)(wo*stride);
    float acc = 0.f;
    #pragma unroll
    for (int k = 0; k < 9; ++k){
        float py = by + (float)(k/3 - 1) + sm[g*18 + k*2 + 0];
        float px = bx + (float)(k%3 - 1) + sm[g*18 + k*2 + 1];
        float msk = smk[g*9 + k];
        float fy = floorf(py), fx = floorf(px);
        float wy = py - fy, wx = px - fx;
        int iy = (int)fy, ix = (int)fx;
        #pragma unroll
        for (int dy = 0; dy < 2; ++dy){
            int yy = iy + dy;
            if (yy < 0 || yy >= H) continue;
            float wgy = dy ? wy : (1.f - wy);
            #pragma unroll
            for (int dx = 0; dx < 2; ++dx){
                int xx = ix + dx;
                if (xx < 0 || xx >= W) continue;
                float wgt = wgy * (dx ? wx : (1.f - wx)) * msk;
                acc += wgt * x[((n*H + yy)*W + xx)*CH + c];
            }
        }
    }
    g_feat[((n*Ho + ho)*Wo + wo)*CH + c] = acc;
}

// ---------------- fused stats: GN mean/var + weighted per-channel means --------
// block = (n, gn-group). weights = separable bilinear row/col mass for the
// (optional) upsample, so downstream attn / dyrelu means are exact.
__global__ void k_stats(int Hs, int Ws, int Hup, int Wup, int upsample, float normw){
    __shared__ float wy[80], wx[80];
    __shared__ float r1[256], r2[256];
    int n = blockIdx.x >> 4, g = blockIdx.x & 15;
    int t = threadIdx.x;
    if (t == 0){
        if (upsample){
            for (int i = 0; i < Hs; ++i) wy[i] = 0.f;
            for (int i = 0; i < Ws; ++i) wx[i] = 0.f;
            float ry = (Hup > 1) ? (float)(Hs - 1)/(float)(Hup - 1) : 0.f;
            float rx = (Wup > 1) ? (float)(Ws - 1)/(float)(Wup - 1) : 0.f;
            for (int j = 0; j < Hup; ++j){
                float c = j*ry; int i0 = (int)floorf(c); float f = c - (float)i0;
                wy[i0] += 1.f - f;
                if (i0 + 1 < Hs) wy[i0+1] += f;
            }
            for (int j = 0; j < Wup; ++j){
                float c = j*rx; int i0 = (int)floorf(c); float f = c - (float)i0;
                wx[i0] += 1.f - f;
                if (i0 + 1 < Ws) wx[i0+1] += f;
            }
        } else {
            for (int i = 0; i < Hs; ++i) wy[i] = 1.f;
            for (int i = 0; i < Ws; ++i) wx[i] = 1.f;
        }
    }
    __syncthreads();

    int HW = Hs*Ws;
    int cc = t & 15;
    int c  = g*16 + cc;
    float s = 0.f, ss = 0.f, wsm = 0.f;
    int h = 0, w = t >> 4;     // initial hw = t>>4 < 16 < Ws
    for (int hw = t >> 4; hw < HW; hw += 16){
        float v = g_feat[(n*HW + hw)*CH + c];
        s += v; ss += v*v;
        wsm += v * wy[h]*wx[w];
        w += 16; if (w >= Ws){ w -= Ws; ++h; }
    }
    r1[t] = s; r2[t] = ss;
    __syncthreads();
    for (int o = 128; o > 0; o >>= 1){
        if (t < o){ r1[t] += r1[t+o]; r2[t] += r2[t+o]; }
        __syncthreads();
    }
    if (t == 0){
        float cnt = (float)(HW*16);
        float mu  = r1[0]/cnt;
        float var = r2[0]/cnt - mu*mu;
        g_gmu[n*16 + g]  = mu;
        g_ginv[n*16 + g] = rsqrtf(var + 1e-5f);
    }
    __syncthreads();
    r1[t] = wsm;
    __syncthreads();
    for (int o = 128; o >= 16; o >>= 1){
        if (t < o) r1[t] += r1[t+o];
        __syncthreads();
    }
    if (t < 16) g_cmean[n*CH + g*16 + t] = r1[t]*normw;
}

// attn scalar + dyrelu pooled-mean accumulation (all analytic from stats)
__global__ void k_attn2(int first, float invl,
                        const float* __restrict__ saw, const float* __restrict__ sab,
                        const float* __restrict__ gam, const float* __restrict__ bet){
    __shared__ float red[256];
    __shared__ float sa;
    int n = blockIdx.x, t = threadIdx.x;
    int g = t >> 4;
    float m = (g_cmean[n*CH + t] - g_gmu[n*16 + g])*g_ginv[n*16 + g]*gam[t] + bet[t];
    red[t] = m*saw[t];
    __syncthreads();
    for (int o = 128; o > 0; o >>= 1){
        if (t < o) red[t] += red[t+o];
        __syncthreads();
    }
    if (t == 0){
        float a = red[0] + sab[0];
        a = fmaxf(a, 0.f);
        a = fminf(fmaxf((a + 3.f)/6.f, 0.f), 1.f);
        sa = a; g_a[n] = a;
    }
    __syncthreads();
    float contrib = sa*m*invl;
    g_y[n*CH + t] = first ? contrib : (g_y[n*CH + t] + contrib);
}

// accumulate (no upsample): GN-apply + attn scale fused
__global__ void k_acc(int HW, int first,
                      const float* __restrict__ gam, const float* __restrict__ bet){
    int total = NB*HW*CH;
    for (int i = blockIdx.x*blockDim.x + threadIdx.x; i < total; i += gridDim.x*blockDim.x){
        int c = i & 255;
        int n = (i >> 8) / HW;
        int g = c >> 4;
        float val = (g_feat[i] - g_gmu[n*16 + g])*g_ginv[n*16 + g]*gam[c] + bet[c];
        float v = g_a[n]*val;
        g_sum[i] = first ? v : (g_sum[i] + v);
    }
}

// accumulate with align-corners bilinear upsample, GN + attn fused (never first)
__global__ void k_acc_up(int Hs, int Ws, int Ho, int Wo,
                         const float* __restrict__ gam, const float* __restrict__ bet){
    int total = NB*Ho*Wo*CH;
    float ry = (Ho > 1) ? (float)(Hs - 1)/(float)(Ho - 1) : 0.f;
    float rx = (Wo > 1) ? (float)(Ws - 1)/(float)(Wo - 1) : 0.f;
    for (int i = blockIdx.x*blockDim.x + threadIdx.x; i < total; i += gridDim.x*blockDim.x){
        int c  = i & 255;
        int hw = i >> 8;
        int w  = hw % Wo;
        int h  = (hw / Wo) % Ho;
        int n  = hw / (Wo*Ho);
        float cy = h*ry, cx = w*rx;
        int y0 = (int)floorf(cy), x0 = (int)floorf(cx);
        int y1 = min(y0 + 1, Hs - 1), x1 = min(x0 + 1, Ws - 1);
        float wyf = cy - (float)y0, wxf = cx - (float)x0;
        const float* f = g_feat;
        float v00 = f[((n*Hs + y0)*Ws + x0)*CH + c];
        float v01 = f[((n*Hs + y0)*Ws + x1)*CH + c];
        float v10 = f[((n*Hs + y1)*Ws + x0)*CH + c];
        float v11 = f[((n*Hs + y1)*Ws + x1)*CH + c];
        float t0 = v00*(1.f - wyf) + v10*wyf;
        float t1 = v01*(1.f - wyf) + v11*wyf;
        float raw = t0*(1.f - wxf) + t1*wxf;
        int g = c >> 4;
        float val = (raw - g_gmu[n*16 + g])*g_ginv[n*16 + g]*gam[c] + bet[c];
        g_sum[i] += g_a[n]*val;
    }
}

__global__ void k_fc1(const float* __restrict__ w1, const float* __restrict__ b1){
    int t = threadIdx.x;
    int n = t / 64, j = t % 64;
    float s = b1[j];
    for (int c = 0; c < CH; ++c) s += g_y[n*CH + c]*w1[j*CH + c];
    g_hbuf[n*64 + j] = fmaxf(s, 0.f);
}

__global__ void k_fc2(const float* __restrict__ w2, const float* __restrict__ b2){
    int og = blockIdx.x*blockDim.x + threadIdx.x;
    if (og >= NB*1024) return;
    int n = og / 1024, o = og % 1024;
    float s = b2[o];
    #pragma unroll
    for (int j = 0; j < 64; ++j) s += g_hbuf[n*64 + j]*w2[o*64 + j];
    float z = fminf(fmaxf(s + 3.f, 0.f), 6.f)*(1.f/6.f);
    int q = o / 256;
    float v;
    if      (q == 0) v = (z - 0.5f)*2.f + 1.f;
    else if (q == 2) v = (z - 0.5f)*2.f;
    else             v = z - 0.5f;
    g_z[og] = v;
}

// dyrelu + NHWC->NCHW tiled transposed write
__global__ void k_out2(int HW, float invl, float* __restrict__ out){
    __shared__ float tile[32][33];
    int n   = blockIdx.z;
    int hw0 = blockIdx.x*32;
    int c0  = blockIdx.y*32;
    int tx = threadIdx.x, ty = threadIdx.y;  // (32,8)
    #pragma unroll
    for (int q = 0; q < 4; ++q){
        int hw = hw0 + ty + q*8;
        float v = (hw < HW) ? g_sum[((size_t)n*HW + hw)*CH + c0 + tx] : 0.f;
        tile[ty + q*8][tx] = v;
    }
    __syncthreads();
    int hw = hw0 + tx;
    if (hw < HW){
        #pragma unroll
        for (int q = 0; q < 4; ++q){
            int cl = ty + q*8;
            int c  = c0 + cl;
            float f  = tile[tx][cl]*invl;
            float a1 = g_z[n*1024 + c];
            float b1 = g_z[n*1024 + 256 + c];
            float a2 = g_z[n*1024 + 512 + c];
            float b2 = g_z[n*1024 + 768 + c];
            out[((size_t)n*CH + c)*HW + hw] = fmaxf(f*a1 + b1, f*a2 + b2);
        }
    }
}

// ---------------- host ----------------
static inline int gsz(int total){ return (total + 255) / 256; }

extern "C" void kernel_launch(void* const* d_in, const int* in_sizes, int n_in,
                              void* d_out, int out_size){
    const float* x0     = (const float*)d_in[0];
    const float* x1     = (const float*)d_in[1];
    const float* x2     = (const float*)d_in[2];
    const float* dw_w_h = (const float*)d_in[3];
    const float* dw_s_h = (const float*)d_in[4];
    const float* dw_b_h = (const float*)d_in[5];
    const float* dw_w_m = (const float*)d_in[6];
    const float* dw_s_m = (const float*)d_in[7];
    const float* dw_b_m = (const float*)d_in[8];
    const float* dw_w_l = (const float*)d_in[9];
    const float* dw_s_l = (const float*)d_in[10];
    const float* dw_b_l = (const float*)d_in[11];
    const float* off_w  = (const float*)d_in[12];
    const float* off_b  = (const float*)d_in[13];
    const float* gn_g_h = (const float*)d_in[14];
    const float* gn_b_h = (const float*)d_in[15];
    const float* gn_g_m = (const float*)d_in[16];
    const float* gn_b_m = (const float*)d_in[17];
    const float* gn_g_l = (const float*)d_in[18];
    const float* gn_b_l = (const float*)d_in[19];
    const float* sa_w   = (const float*)d_in[20];
    const float* sa_b   = (const float*)d_in[21];
    const float* fc1_w  = (const float*)d_in[22];
    const float* fc1_b  = (const float*)d_in[23];
    const float* fc2_w  = (const float*)d_in[24];
    const float* fc2_b  = (const float*)d_in[25];
    float* out = (float*)d_out;

    const int OM_SMEM = (3*CH*24 + 64*108)*4;   // 101376 B
    cudaFuncSetAttribute(k_om2<1,20,4>, cudaFuncAttributeMaxDynamicSharedMemorySize, OM_SMEM);
    cudaFuncSetAttribute(k_om2<2,10,2>, cudaFuncAttributeMaxDynamicSharedMemorySize, OM_SMEM);

    // input transposes (tiled) + weight transpose
    k_tr2<<<dim3((6400+31)/32, 8, NB), dim3(32,8)>>>(x0, 0, 6400);
    k_tr2<<<dim3((1600+31)/32, 8, NB), dim3(32,8)>>>(x1, 1, 1600);
    k_tr2<<<dim3(( 400+31)/32, 8, NB), dim3(32,8)>>>(x2, 2,  400);
    k_wt<<<gsz(576*OMC), 256>>>(off_w);

    auto branch = [&](int sel, int Hs, int Ws,
                      const float* dww, const float* dws, const float* dwb,
                      const float* gng, const float* gnb,
                      int softmax, int stride, int Ho, int Wo,
                      int upHo, int upWo, int first, float invl){
        k_dw<<<gsz(NB*Hs*Ws*CH), 256>>>(sel, Hs, Ws, dww, dws, dwb);
        if (stride == 1){
            int nt = (Wo + 19)/20;
            k_om2<1,20,4><<<NB*Ho*nt, 192, OM_SMEM>>>(Hs, Ws, Ho, Wo, off_b);
        } else {
            int nt = (Wo + 9)/10;
            k_om2<2,10,2><<<NB*Ho*nt, 192, OM_SMEM>>>(Hs, Ws, Ho, Wo, off_b);
        }
        k_samp<<<NB*Ho*Wo, 256>>>(sel, Hs, Ws, Ho, Wo, stride, softmax);
        if (upHo){
            k_stats<<<NB*16, 256>>>(Ho, Wo, upHo, upWo, 1, 1.f/((float)upHo*(float)upWo));
        } else {
            k_stats<<<NB*16, 256>>>(Ho, Wo, 0, 0, 0, 1.f/((float)Ho*(float)Wo));
        }
        k_attn2<<<NB, 256>>>(first, invl, sa_w, sa_b, gng, gnb);
        if (upHo){
            k_acc_up<<<gsz(NB*upHo*upWo*CH), 256>>>(Ho, Wo, upHo, upWo, gng, gnb);
        } else {
            k_acc<<<gsz(NB*Ho*Wo*CH), 256>>>(Ho*Wo, first, gng, gnb);
        }
    };

    auto finish = [&](int Ho, int Wo, int nlvls, float* optr){
        float invl = 1.f / (float)nlvls;
        k_fc1<<<1, 256>>>(fc1_w, fc1_b);
        k_fc2<<<16, 256>>>(fc2_w, fc2_b);
        int HW = Ho*Wo;
        k_out2<<<dim3((HW+31)/32, 8, NB), dim3(32,8)>>>(HW, invl, optr);
    };

    // level 0 (80x80): mid(x0) + high(x1 -> up 80)
    branch(0, 80, 80, dw_w_m, dw_s_m, dw_b_m, gn_g_m, gn_b_m, 0, 1, 80, 80, 0,  0,  1, 0.5f);
    branch(1, 40, 40, dw_w_h, dw_s_h, dw_b_h, gn_g_h, gn_b_h, 1, 1, 40, 40, 80, 80, 0, 0.5f);
    finish(80, 80, 2, out);

    // level 1 (40x40): mid(x1) + low(x0,s2) + high(x2 -> up 40)
    branch(1, 40, 40, dw_w_m, dw_s_m, dw_b_m, gn_g_m, gn_b_m, 0, 1, 40, 40, 0,  0,  1, 1.f/3.f);
    branch(0, 80, 80, dw_w_l, dw_s_l, dw_b_l, gn_g_l, gn_b_l, 1, 2, 40, 40, 0,  0,  0, 1.f/3.f);
    branch(2, 20, 20, dw_w_h, dw_s_h, dw_b_h, gn_g_h, gn_b_h, 1, 1, 20, 20, 40, 40, 0, 1.f/3.f);
    finish(40, 40, 3, out + (size_t)NB*CH*80*80);

    // level 2 (20x20): mid(x2) + low(x1,s2)
    branch(2, 20, 20, dw_w_m, dw_s_m, dw_b_m, gn_g_m, gn_b_m, 0, 1, 20, 20, 0, 0, 1, 0.5f);
    branch(1, 40, 40, dw_w_l, dw_s_l, dw_b_l, gn_g_l, gn_b_l, 1, 2, 20, 20, 0, 0, 0, 0.5f);
    finish(20, 20, 2, out + (size_t)NB*CH*80*80 + (size_t)NB*CH*40*40);
}

// round 3
// speedup vs baseline: 4.5438x; 1.1883x over previous
#include <cuda_runtime.h>
#include <math.h>

#define NB   4
#define CH   256
#define OMC  108

// ---------------- scratch ----------------
__device__ float g_x0[NB*80*80*CH];
__device__ float g_x1[NB*40*40*CH];
__device__ float g_x2[NB*20*20*CH];
__device__ float g_dw[NB*80*80*CH];
__device__ float g_om[NB*80*80*OMC];
__device__ float g_feat[NB*80*80*CH];
__device__ float g_sum[NB*80*80*CH];
__device__ float g_wT2[3*192*112];      // [dy][ic*3+dx][slot(4 groups x 28)]
__device__ float g_a[NB];
__device__ float g_y[NB*CH];
__device__ float g_z[NB*1024];
__device__ float g_cmean[NB*CH];
__device__ float g_gmu[NB*16];
__device__ float g_ginv[NB*16];

__device__ __forceinline__ const float* pick_x(int s){
    return s==0 ? g_x0 : (s==1 ? g_x1 : g_x2);
}
__device__ __forceinline__ float* pick_xm(int s){
    return s==0 ? g_x0 : (s==1 ? g_x1 : g_x2);
}

// ---------------- NCHW -> NHWC tiled transpose ----------------
__global__ void k_tr2(const float* __restrict__ in, int sel, int HW){
    __shared__ float tile[32][33];
    float* out = pick_xm(sel);
    int n  = blockIdx.z;
    int hw0 = blockIdx.x*32;
    int c0  = blockIdx.y*32;
    int tx = threadIdx.x, ty = threadIdx.y;  // (32,8)
    #pragma unroll
    for (int q = 0; q < 4; ++q){
        int c = c0 + ty + q*8;
        int hw = hw0 + tx;
        float v = (hw < HW) ? in[((size_t)n*CH + c)*HW + hw] : 0.f;
        tile[ty + q*8][tx] = v;
    }
    __syncthreads();
    #pragma unroll
    for (int q = 0; q < 4; ++q){
        int hw = hw0 + ty + q*8;
        int c  = c0 + tx;
        if (hw < HW) out[((size_t)n*HW + hw)*CH + c] = tile[tx][ty + q*8];
    }
}

// weight transform: pad each group of 27 oc to 28 slots, layout [dy][ic*3+dx][112]
__global__ void k_wt2(const float* __restrict__ ow){
    int i = blockIdx.x*blockDim.x + threadIdx.x;
    if (i >= 3*192*112) return;
    int slot = i % 112;
    int r    = (i / 112) % 192;
    int dy   = i / (112*192);
    int ic = r/3, dx = r%3;
    int g = slot/28, jj = slot%28;
    float v = 0.f;
    if (jj < 27){
        int oc = g*27 + jj;
        v = ow[oc*576 + ic*9 + dy*3 + dx];
    }
    g_wT2[i] = v;
}

// depthwise 3x3 + scale/bias + SiLU, float4, weights hoisted to regs
__global__ void k_dw4(int sel, int H, int W,
                      const float* __restrict__ wgt,
                      const float* __restrict__ sc,
                      const float* __restrict__ bi){
    const float* x = pick_x(sel);
    int q  = threadIdx.x & 63;
    int c0 = q*4;
    float wr[9][4];
    #pragma unroll
    for (int tp = 0; tp < 9; ++tp)
        #pragma unroll
        for (int j = 0; j < 4; ++j) wr[tp][j] = wgt[(c0+j)*9 + tp];
    float4 s4 = *(const float4*)(sc + c0);
    float4 b4 = *(const float4*)(bi + c0);
    int n = blockIdx.y;
    int HW = H*W;
    int lane = threadIdx.x >> 6;   // 0..3 pixel slots
    for (int hw = blockIdx.x*4 + lane; hw < HW; hw += gridDim.x*4){
        int w = hw % W, h = hw / W;
        float4 acc = make_float4(0,0,0,0);
        #pragma unroll
        for (int dy = 0; dy < 3; ++dy){
            int yy = h + dy - 1;
            if (yy < 0 || yy >= H) continue;
            #pragma unroll
            for (int dx = 0; dx < 3; ++dx){
                int xx = w + dx - 1;
                if (xx < 0 || xx >= W) continue;
                float4 v = *(const float4*)(x + ((size_t)(n*H+yy)*W + xx)*CH + c0);
                int tp = dy*3 + dx;
                acc.x += v.x*wr[tp][0]; acc.y += v.y*wr[tp][1];
                acc.z += v.z*wr[tp][2]; acc.w += v.w*wr[tp][3];
            }
        }
        float4 o;
        float t0 = acc.x*s4.x + b4.x; o.x = t0/(1.f+expf(-t0));
        float t1 = acc.y*s4.y + b4.y; o.y = t1/(1.f+expf(-t1));
        float t2 = acc.z*s4.z + b4.z; o.z = t2/(1.f+expf(-t2));
        float t3 = acc.w*s4.w + b4.w; o.w = t3/(1.f+expf(-t3));
        *(float4*)(g_dw + ((size_t)n*HW + hw)*CH + c0) = o;
    }
}

// ---------------- grouped conv 256->108, dy-windowed float4 ----------------
template<int STRIDE, int PXO, int TPX>
__global__ void __launch_bounds__(160, 2)
k_om2(int H, int W, int Ho, int Wo, const float* __restrict__ ob){
    constexpr int PWP = 28;
    constexpr int PW  = (PXO-1)*STRIDE + 3;
    constexpr int PXQ = PXO/TPX;
    static_assert(PW <= PWP, "patch width");
    extern __shared__ float sh[];
    float* patch = sh;             // [256][PWP]
    float* wsl   = sh + 256*PWP;   // [192][112]

    int nt   = (Wo + PXO - 1)/PXO;
    int b    = blockIdx.x;
    int tile = b % nt;
    int ho   = (b/nt) % Ho;
    int n    = b/(nt*Ho);
    int wo0  = tile*PXO;
    int hsrc = ho*STRIDE;
    int wsrc0= wo0*STRIDE;

    int t   = threadIdx.x;
    int pxq = t % PXQ;
    int ocT = t / PXQ;
    bool act = ocT < 28;
    int g    = act ? ocT/7 : 0;
    int li   = act ? ocT%7 : 0;
    int woff = g*28 + li*4;
    int cb   = g*64;
    int xb   = pxq*TPX*STRIDE;

    float4 acc[TPX];
    #pragma unroll
    for (int p = 0; p < TPX; ++p) acc[p] = make_float4(0,0,0,0);

    for (int dy = 0; dy < 3; ++dy){
        __syncthreads();
        int gy = hsrc + dy - 1;
        for (int i = t; i < PW*256; i += 160){
            int c = i & 255, xx = i >> 8;
            int gx = wsrc0 + xx - 1;
            float v = 0.f;
            if (gy >= 0 && gy < H && gx >= 0 && gx < W)
                v = g_dw[((size_t)(n*H+gy)*W + gx)*CH + c];
            patch[c*PWP + xx] = v;
        }
        {
            const float4* src = (const float4*)(g_wT2 + dy*192*112);
            float4* dst = (float4*)wsl;
            for (int i = t; i < 192*112/4; i += 160) dst[i] = src[i];
        }
        __syncthreads();
        if (act){
            #pragma unroll 4
            for (int ic = 0; ic < 64; ++ic){
                const float* pr = patch + (cb+ic)*PWP + xb;
                float f[8];
                *(float4*)(f)   = *(const float4*)(pr);
                *(float4*)(f+4) = *(const float4*)(pr+4);
                const float* wb = wsl + (ic*3)*112 + woff;
                #pragma unroll
                for (int dx = 0; dx < 3; ++dx){
                    float4 wv = *(const float4*)(wb + dx*112);
                    #pragma unroll
                    for (int p = 0; p < TPX; ++p){
                        float s = f[dx + p*STRIDE];
                        acc[p].x += s*wv.x; acc[p].y += s*wv.y;
                        acc[p].z += s*wv.z; acc[p].w += s*wv.w;
                    }
                }
            }
        }
    }
    if (act){
        float bj[4];
        #pragma unroll
        for (int j = 0; j < 4; ++j){
            int jj = li*4 + j;
            bj[j] = (jj < 27) ? ob[g*27 + jj] : 0.f;
        }
        #pragma unroll
        for (int p = 0; p < TPX; ++p){
            int wo = wo0 + pxq*TPX + p;
            if (wo < Wo){
                size_t base = ((size_t)(n*Ho+ho)*Wo + wo)*OMC + g*27 + li*4;
                float av[4] = {acc[p].x, acc[p].y, acc[p].z, acc[p].w};
                #pragma unroll
                for (int j = 0; j < 4; ++j)
                    if (li*4 + j < 27) g_om[base + j] = av[j] + bj[j];
            }
        }
    }
}

// ---------------- DCNv3 sampler: 4 pixels/block, float4 channels ----------------
__global__ void k_samp4(int sel, int H, int W, int Ho, int Wo, int stride, int use_softmax){
    __shared__ float som[4][OMC];
    __shared__ float smk[4][36];
    const float* x = pick_x(sel);
    int HW = Ho*Wo;
    int tiles = HW >> 2;
    int n  = blockIdx.x / tiles;
    int p0 = (blockIdx.x % tiles) * 4;
    int t  = threadIdx.x;

    for (int i = t; i < 4*OMC; i += 256)
        som[i/OMC][i%OMC] = g_om[((size_t)n*HW + p0 + i/OMC)*OMC + i%OMC];
    __syncthreads();

    if (use_softmax){
        if (t < 16){
            int pp = t >> 2, gg = t & 3;
            float mx = -1e30f;
            #pragma unroll
            for (int k = 0; k < 9; ++k) mx = fmaxf(mx, som[pp][72 + gg*9 + k]);
            float e[9], s = 0.f;
            #pragma unroll
            for (int k = 0; k < 9; ++k){ e[k] = expf(som[pp][72 + gg*9 + k] - mx); s += e[k]; }
            float inv = 1.f/s;
            #pragma unroll
            for (int k = 0; k < 9; ++k) smk[pp][gg*9 + k] = e[k]*inv;
        }
    } else {
        for (int i = t; i < 4*36; i += 256)
            smk[i/36][i%36] = 1.f/(1.f + expf(-som[i/36][72 + i%36]));
    }
    __syncthreads();

    int pix = t >> 6, q = t & 63, c0 = q*4, g = q >> 4;
    int hw = p0 + pix;
    int wo = hw % Wo, ho = hw / Wo;
    float by = (float)(ho*stride), bx = (float)(wo*stride);
    float4 acc = make_float4(0,0,0,0);
    #pragma unroll
    for (int k = 0; k < 9; ++k){
        float py = by + (float)(k/3 - 1) + som[pix][g*18 + k*2];
        float px = bx + (float)(k%3 - 1) + som[pix][g*18 + k*2 + 1];
        float m  = smk[pix][g*9 + k];
        float fy = floorf(py), fx = floorf(px);
        float wy = py - fy, wx = px - fx;
        int iy = (int)fy, ix = (int)fx;
        #pragma unroll
        for (int d0 = 0; d0 < 2; ++d0){
            int yy = iy + d0;
            if (yy < 0 || yy >= H) continue;
            float wgy = d0 ? wy : (1.f - wy);
            #pragma unroll
            for (int d1 = 0; d1 < 2; ++d1){
                int xx = ix + d1;
                if (xx < 0 || xx >= W) continue;
                float wt = wgy*(d1 ? wx : (1.f - wx))*m;
                float4 v = *(const float4*)(x + ((size_t)(n*H+yy)*W + xx)*CH + c0);
                acc.x += wt*v.x; acc.y += wt*v.y;
                acc.z += wt*v.z; acc.w += wt*v.w;
            }
        }
    }
    *(float4*)(g_feat + ((size_t)n*HW + hw)*CH + c0) = acc;
}

// ---------------- fused stats (float4): GN mean/var + weighted channel means ----
__global__ void k_stats4(int Hs, int Ws, int Hup, int Wup, int ups, float normw){
    __shared__ float wy[80], wx[80];
    __shared__ float r1[256], r2[256];
    __shared__ float4 rw[256];
    int n = blockIdx.x >> 4, g = blockIdx.x & 15;
    int t = threadIdx.x;
    if (t == 0){
        if (ups){
            for (int i = 0; i < Hs; ++i) wy[i] = 0.f;
            for (int i = 0; i < Ws; ++i) wx[i] = 0.f;
            float ry = (Hup > 1) ? (float)(Hs-1)/(float)(Hup-1) : 0.f;
            float rx = (Wup > 1) ? (float)(Ws-1)/(float)(Wup-1) : 0.f;
            for (int j = 0; j < Hup; ++j){
                float c = j*ry; int i0 = (int)floorf(c); float f = c - (float)i0;
                wy[i0] += 1.f - f;
                if (i0 + 1 < Hs) wy[i0+1] += f;
            }
            for (int j = 0; j < Wup; ++j){
                float c = j*rx; int i0 = (int)floorf(c); float f = c - (float)i0;
                wx[i0] += 1.f - f;
                if (i0 + 1 < Ws) wx[i0+1] += f;
            }
        } else {
            for (int i = 0; i < Hs; ++i) wy[i] = 1.f;
            for (int i = 0; i < Ws; ++i) wx[i] = 1.f;
        }
    }
    __syncthreads();

    int HW = Hs*Ws;
    int q  = t & 3;
    int c0 = g*16 + q*4;
    float4 s4 = make_float4(0,0,0,0), w4 = make_float4(0,0,0,0);
    float ss = 0.f;
    int hw0 = t >> 2;
    int h = hw0 / Ws, w = hw0 % Ws;
    for (int hw = hw0; hw < HW; hw += 64){
        float4 v = *(const float4*)(g_feat + ((size_t)n*HW + hw)*CH + c0);
        s4.x += v.x; s4.y += v.y; s4.z += v.z; s4.w += v.w;
        ss += v.x*v.x + v.y*v.y + v.z*v.z + v.w*v.w;
        float ww = wy[h]*wx[w];
        w4.x += v.x*ww; w4.y += v.y*ww; w4.z += v.z*ww; w4.w += v.w*ww;
        w += 64; while (w >= Ws){ w -= Ws; ++h; }
    }
    r1[t] = s4.x + s4.y + s4.z + s4.w;
    r2[t] = ss;
    rw[t] = w4;
    __syncthreads();
    for (int o = 128; o >= 4; o >>= 1){
        if (t < o){
            r1[t] += r1[t+o]; r2[t] += r2[t+o];
            rw[t].x += rw[t+o].x; rw[t].y += rw[t+o].y;
            rw[t].z += rw[t+o].z; rw[t].w += rw[t+o].w;
        }
        __syncthreads();
    }
    if (t == 0){
        float s  = r1[0] + r1[1] + r1[2] + r1[3];
        float sq = r2[0] + r2[1] + r2[2] + r2[3];
        float cnt = (float)HW*16.f;
        float mu  = s/cnt;
        float var = sq/cnt - mu*mu;
        g_gmu[n*16 + g]  = mu;
        g_ginv[n*16 + g] = rsqrtf(var + 1e-5f);
    }
    if (t < 4){
        float4 wv = rw[t];
        int c = n*CH + g*16 + t*4;
        g_cmean[c]   = wv.x*normw; g_cmean[c+1] = wv.y*normw;
        g_cmean[c+2] = wv.z*normw; g_cmean[c+3] = wv.w*normw;
    }
}

// attn scalar + dyrelu pooled-mean accumulation
__global__ void k_attn2(int first, float invl,
                        const float* __restrict__ saw, const float* __restrict__ sab,
                        const float* __restrict__ gam, const float* __restrict__ bet){
    __shared__ float red[256];
    __shared__ float sa;
    int n = blockIdx.x, t = threadIdx.x;
    int g = t >> 4;
    float m = (g_cmean[n*CH + t] - g_gmu[n*16 + g])*g_ginv[n*16 + g]*gam[t] + bet[t];
    red[t] = m*saw[t];
    __syncthreads();
    for (int o = 128; o > 0; o >>= 1){
        if (t < o) red[t] += red[t+o];
        __syncthreads();
    }
    if (t == 0){
        float a = red[0] + sab[0];
        a = fmaxf(a, 0.f);
        a = fminf(fmaxf((a + 3.f)/6.f, 0.f), 1.f);
        sa = a; g_a[n] = a;
    }
    __syncthreads();
    float contrib = sa*m*invl;
    g_y[n*CH + t] = first ? contrib : (g_y[n*CH + t] + contrib);
}

// accumulate (no upsample), float4, GN + attn fused
__global__ void k_acc4(int HW, int first,
                       const float* __restrict__ gam, const float* __restrict__ bet){
    int n = blockIdx.y;
    int idx = blockIdx.x*256 + threadIdx.x;
    if (idx >= HW*64) return;
    int q = idx & 63, hw = idx >> 6;
    int c0 = q*4, g = q >> 2;
    float mu = g_gmu[n*16 + g], inv = g_ginv[n*16 + g], a = g_a[n];
    float4 v  = *(const float4*)(g_feat + ((size_t)n*HW + hw)*CH + c0);
    float4 g4 = *(const float4*)(gam + c0);
    float4 b4 = *(const float4*)(bet + c0);
    float4 r;
    r.x = a*((v.x - mu)*inv*g4.x + b4.x);
    r.y = a*((v.y - mu)*inv*g4.y + b4.y);
    r.z = a*((v.z - mu)*inv*g4.z + b4.z);
    r.w = a*((v.w - mu)*inv*g4.w + b4.w);
    float* dst = g_sum + ((size_t)n*HW + hw)*CH + c0;
    if (first) *(float4*)dst = r;
    else {
        float4 o = *(const float4*)dst;
        o.x += r.x; o.y += r.y; o.z += r.z; o.w += r.w;
        *(float4*)dst = o;
    }
}

// accumulate with bilinear upsample, float4, GN + attn fused (never first)
__global__ void k_acc_up4(int Hs, int Ws, int Ho, int Wo,
                          const float* __restrict__ gam, const float* __restrict__ bet){
    int n = blockIdx.y;
    int HWo = Ho*Wo;
    int idx = blockIdx.x*256 + threadIdx.x;
    if (idx >= HWo*64) return;
    int q = idx & 63, hw = idx >> 6;
    int c0 = q*4, g = q >> 2;
    int w = hw % Wo, h = hw / Wo;
    float ry = (Ho > 1) ? (float)(Hs-1)/(float)(Ho-1) : 0.f;
    float rx = (Wo > 1) ? (float)(Ws-1)/(float)(Wo-1) : 0.f;
    float cy = h*ry, cx = w*rx;
    int y0 = (int)floorf(cy), x0 = (int)floorf(cx);
    int y1 = min(y0+1, Hs-1), x1 = min(x0+1, Ws-1);
    float wyf = cy - (float)y0, wxf = cx - (float)x0;
    const float* f = g_feat;
    float4 v00 = *(const float4*)(f + ((size_t)(n*Hs+y0)*Ws + x0)*CH + c0);
    float4 v01 = *(const float4*)(f + ((size_t)(n*Hs+y0)*Ws + x1)*CH + c0);
    float4 v10 = *(const float4*)(f + ((size_t)(n*Hs+y1)*Ws + x0)*CH + c0);
    float4 v11 = *(const float4*)(f + ((size_t)(n*Hs+y1)*Ws + x1)*CH + c0);
    float a0 = (1.f-wyf)*(1.f-wxf), a1 = (1.f-wyf)*wxf, a2 = wyf*(1.f-wxf), a3 = wyf*wxf;
    float4 raw;
    raw.x = v00.x*a0 + v01.x*a1 + v10.x*a2 + v11.x*a3;
    raw.y = v00.y*a0 + v01.y*a1 + v10.y*a2 + v11.y*a3;
    raw.z = v00.z*a0 + v01.z*a1 + v10.z*a2 + v11.z*a3;
    raw.w = v00.w*a0 + v01.w*a1 + v10.w*a2 + v11.w*a3;
    float mu = g_gmu[n*16 + g], inv = g_ginv[n*16 + g], a = g_a[n];
    float4 g4 = *(const float4*)(gam + c0);
    float4 b4 = *(const float4*)(bet + c0);
    float* dst = g_sum + ((size_t)n*HWo + hw)*CH + c0;
    float4 o = *(const float4*)dst;
    o.x += a*((raw.x - mu)*inv*g4.x + b4.x);
    o.y += a*((raw.y - mu)*inv*g4.y + b4.y);
    o.z += a*((raw.z - mu)*inv*g4.z + b4.z);
    o.w += a*((raw.w - mu)*inv*g4.w + b4.w);
    *(float4*)dst = o;
}

// merged fc1+fc2 (dyrelu coefficients)
__global__ void k_fc(const float* __restrict__ w1, const float* __restrict__ b1,
                     const float* __restrict__ w2, const float* __restrict__ b2){
    __shared__ float h[4][64];
    int t = threadIdx.x;
    int n = t >> 6, j = t & 63;
    float s = b1[j];
    const float* wr = w1 + j*CH;
    for (int c = 0; c < CH; ++c) s += g_y[n*CH + c]*wr[c];
    h[n][j] = fmaxf(s, 0.f);
    __syncthreads();
    for (int og = t; og < NB*1024; og += 256){
        int nn = og >> 10, o = og & 1023;
        float s2 = b2[o];
        const float* w2r = w2 + o*64;
        #pragma unroll 16
        for (int j2 = 0; j2 < 64; ++j2) s2 += h[nn][j2]*w2r[j2];
        float z = fminf(fmaxf(s2 + 3.f, 0.f), 6.f)*(1.f/6.f);
        int qd = o >> 8;
        float v;
        if      (qd == 0) v = (z - 0.5f)*2.f + 1.f;
        else if (qd == 2) v = (z - 0.5f)*2.f;
        else              v = z - 0.5f;
        g_z[og] = v;
    }
}

// dyrelu + NHWC->NCHW tiled transposed write
__global__ void k_out2(int HW, float invl, float* __restrict__ out){
    __shared__ float tile[32][33];
    int n   = blockIdx.z;
    int hw0 = blockIdx.x*32;
    int c0  = blockIdx.y*32;
    int tx = threadIdx.x, ty = threadIdx.y;
    #pragma unroll
    for (int q = 0; q < 4; ++q){
        int hw = hw0 + ty + q*8;
        float v = (hw < HW) ? g_sum[((size_t)n*HW + hw)*CH + c0 + tx] : 0.f;
        tile[ty + q*8][tx] = v;
    }
    __syncthreads();
    int hw = hw0 + tx;
    if (hw < HW){
        #pragma unroll
        for (int q = 0; q < 4; ++q){
            int cl = ty + q*8;
            int c  = c0 + cl;
            float f  = tile[tx][cl]*invl;
            float a1 = g_z[n*1024 + c];
            float b1 = g_z[n*1024 + 256 + c];
            float a2 = g_z[n*1024 + 512 + c];
            float b2 = g_z[n*1024 + 768 + c];
            out[((size_t)n*CH + c)*HW + hw] = fmaxf(f*a1 + b1, f*a2 + b2);
        }
    }
}

// ---------------- host ----------------
extern "C" void kernel_launch(void* const* d_in, const int* in_sizes, int n_in,
                              void* d_out, int out_size){
    const float* x0     = (const float*)d_in[0];
    const float* x1     = (const float*)d_in[1];
    const float* x2     = (const float*)d_in[2];
    const float* dw_w_h = (const float*)d_in[3];
    const float* dw_s_h = (const float*)d_in[4];
    const float* dw_b_h = (const float*)d_in[5];
    const float* dw_w_m = (const float*)d_in[6];
    const float* dw_s_m = (const float*)d_in[7];
    const float* dw_b_m = (const float*)d_in[8];
    const float* dw_w_l = (const float*)d_in[9];
    const float* dw_s_l = (const float*)d_in[10];
    const float* dw_b_l = (const float*)d_in[11];
    const float* off_w  = (const float*)d_in[12];
    const float* off_b  = (const float*)d_in[13];
    const float* gn_g_h = (const float*)d_in[14];
    const float* gn_b_h = (const float*)d_in[15];
    const float* gn_g_m = (const float*)d_in[16];
    const float* gn_b_m = (const float*)d_in[17];
    const float* gn_g_l = (const float*)d_in[18];
    const float* gn_b_l = (const float*)d_in[19];
    const float* sa_w   = (const float*)d_in[20];
    const float* sa_b   = (const float*)d_in[21];
    const float* fc1_w  = (const float*)d_in[22];
    const float* fc1_b  = (const float*)d_in[23];
    const float* fc2_w  = (const float*)d_in[24];
    const float* fc2_b  = (const float*)d_in[25];
    float* out = (float*)d_out;

    const int OM_SMEM = (256*28 + 192*112)*4;   // 114688 B
    cudaFuncSetAttribute(k_om2<1,20,4>, cudaFuncAttributeMaxDynamicSharedMemorySize, OM_SMEM);
    cudaFuncSetAttribute(k_om2<2,10,2>, cudaFuncAttributeMaxDynamicSharedMemorySize, OM_SMEM);

    auto dw = [&](int sel, int H, int W, const float* ww, const float* ss, const float* bb){
        int HW = H*W;
        int grid = (HW + 31)/32;   // ~8 pixels per thread
        k_dw4<<<dim3(grid, NB), 256>>>(sel, H, W, ww, ss, bb);
    };
    auto om = [&](int H, int W, int Ho, int Wo, int stride){
        if (stride == 1){
            int nt = (Wo + 19)/20;
            k_om2<1,20,4><<<NB*Ho*nt, 160, OM_SMEM>>>(H, W, Ho, Wo, off_b);
        } else {
            int nt = (Wo + 9)/10;
            k_om2<2,10,2><<<NB*Ho*nt, 160, OM_SMEM>>>(H, W, Ho, Wo, off_b);
        }
    };
    auto tail = [&](int sel, int Hs, int Ws, int Ho, int Wo, int stride, int softmax,
                    int upHo, int upWo, int first, float invl,
                    const float* gng, const float* gnb){
        k_samp4<<<NB*(Ho*Wo/4), 256>>>(sel, Hs, Ws, Ho, Wo, stride, softmax);
        if (upHo)
            k_stats4<<<NB*16, 256>>>(Ho, Wo, upHo, upWo, 1, 1.f/((float)upHo*(float)upWo));
        else
            k_stats4<<<NB*16, 256>>>(Ho, Wo, 0, 0, 0, 1.f/((float)Ho*(float)Wo));
        k_attn2<<<NB, 256>>>(first, invl, sa_w, sa_b, gng, gnb);
        if (upHo)
            k_acc_up4<<<dim3(upHo*upWo/4, NB), 256>>>(Ho, Wo, upHo, upWo, gng, gnb);
        else
            k_acc4<<<dim3(Ho*Wo/4, NB), 256>>>(Ho*Wo, first, gng, gnb);
    };
    auto finish = [&](int Ho, int Wo, int nlvls, float* optr){
        float invl = 1.f/(float)nlvls;
        k_fc<<<1, 256>>>(fc1_w, fc1_b, fc2_w, fc2_b);
        int HW = Ho*Wo;
        k_out2<<<dim3((HW+31)/32, 8, NB), dim3(32,8)>>>(HW, invl, optr);
    };

    // ---- level 0 mid branch first so ncu (-s 5) profiles k_om2 ----
    k_tr2<<<dim3(200, 8, NB), dim3(32,8)>>>(x0, 0, 6400);            // 0
    dw(0, 80, 80, dw_w_m, dw_s_m, dw_b_m);                           // 1
    k_wt2<<<(3*192*112 + 255)/256, 256>>>(off_w);                    // 2
    om(80, 80, 80, 80, 1);                                           // 3 <- profiled
    tail(0, 80, 80, 80, 80, 1, 0, 0, 0, 1, 0.5f, gn_g_m, gn_b_m);

    k_tr2<<<dim3(50, 8, NB), dim3(32,8)>>>(x1, 1, 1600);
    k_tr2<<<dim3(13, 8, NB), dim3(32,8)>>>(x2, 2,  400);

    // level 0 high: x1 -> 40x40 -> up 80x80
    dw(1, 40, 40, dw_w_h, dw_s_h, dw_b_h);
    om(40, 40, 40, 40, 1);
    tail(1, 40, 40, 40, 40, 1, 1, 80, 80, 0, 0.5f, gn_g_h, gn_b_h);
    finish(80, 80, 2, out);

    // level 1: mid(x1) + low(x0,s2) + high(x2 -> up 40)
    dw(1, 40, 40, dw_w_m, dw_s_m, dw_b_m);
    om(40, 40, 40, 40, 1);
    tail(1, 40, 40, 40, 40, 1, 0, 0, 0, 1, 1.f/3.f, gn_g_m, gn_b_m);

    dw(0, 80, 80, dw_w_l, dw_s_l, dw_b_l);
    om(80, 80, 40, 40, 2);
    tail(0, 80, 80, 40, 40, 2, 1, 0, 0, 0, 1.f/3.f, gn_g_l, gn_b_l);

    dw(2, 20, 20, dw_w_h, dw_s_h, dw_b_h);
    om(20, 20, 20, 20, 1);
    tail(2, 20, 20, 20, 20, 1, 1, 40, 40, 0, 1.f/3.f, gn_g_h, gn_b_h);
    finish(40, 40, 3, out + (size_t)NB*CH*80*80);

    // level 2: mid(x2) + low(x1,s2)
    dw(2, 20, 20, dw_w_m, dw_s_m, dw_b_m);
    om(20, 20, 20, 20, 1);
    tail(2, 20, 20, 20, 20, 1, 0, 0, 0, 1, 0.5f, gn_g_m, gn_b_m);

    dw(1, 40, 40, dw_w_l, dw_s_l, dw_b_l);
    om(40, 40, 20, 20, 2);
    tail(1, 40, 40, 20, 20, 2, 1, 0, 0, 0, 0.5f, gn_g_l, gn_b_l);
    finish(20, 20, 2, out + (size_t)NB*CH*80*80 + (size_t)NB*CH*40*40);
}

// round 4
// speedup vs baseline: 5.0941x; 1.1211x over previous
#include <cuda_runtime.h>
#include <math.h>

#define NB   4
#define CH   256
#define OMC  108

// ---------------- scratch ----------------
__device__ float g_x0[NB*80*80*CH];
__device__ float g_x1[NB*40*40*CH];
__device__ float g_x2[NB*20*20*CH];
__device__ float g_dw[NB*80*80*CH];
__device__ float g_om[NB*80*80*OMC];
__device__ float g_feat[NB*80*80*CH];
__device__ float g_sum[NB*80*80*CH];
__device__ float g_wT2[3*192*112];      // [dy][ic*3+dx][slot(4 groups x 28)]
__device__ float g_a[NB];
__device__ float g_y[NB*CH];
__device__ float g_z[NB*1024];
__device__ float g_cmean[NB*CH];
__device__ float g_gmu[NB*16];
__device__ float g_ginv[NB*16];

__device__ __forceinline__ const float* pick_x(int s){
    return s==0 ? g_x0 : (s==1 ? g_x1 : g_x2);
}
__device__ __forceinline__ float* pick_xm(int s){
    return s==0 ? g_x0 : (s==1 ? g_x1 : g_x2);
}

// ---------------- NCHW -> NHWC tiled transpose ----------------
__global__ void k_tr2(const float* __restrict__ in, int sel, int HW){
    __shared__ float tile[32][33];
    float* out = pick_xm(sel);
    int n  = blockIdx.z;
    int hw0 = blockIdx.x*32;
    int c0  = blockIdx.y*32;
    int tx = threadIdx.x, ty = threadIdx.y;  // (32,8)
    #pragma unroll
    for (int q = 0; q < 4; ++q){
        int c = c0 + ty + q*8;
        int hw = hw0 + tx;
        float v = (hw < HW) ? in[((size_t)n*CH + c)*HW + hw] : 0.f;
        tile[ty + q*8][tx] = v;
    }
    __syncthreads();
    #pragma unroll
    for (int q = 0; q < 4; ++q){
        int hw = hw0 + ty + q*8;
        int c  = c0 + tx;
        if (hw < HW) out[((size_t)n*HW + hw)*CH + c] = tile[tx][ty + q*8];
    }
}

// weight transform: pad each group of 27 oc to 28 slots, layout [dy][ic*3+dx][112]
__global__ void k_wt2(const float* __restrict__ ow){
    int i = blockIdx.x*blockDim.x + threadIdx.x;
    if (i >= 3*192*112) return;
    int slot = i % 112;
    int r    = (i / 112) % 192;
    int dy   = i / (112*192);
    int ic = r/3, dx = r%3;
    int g = slot/28, jj = slot%28;
    float v = 0.f;
    if (jj < 27){
        int oc = g*27 + jj;
        v = ow[oc*576 + ic*9 + dy*3 + dx];
    }
    g_wT2[i] = v;
}

// depthwise 3x3 + scale/bias + SiLU, float4, weights hoisted to regs
__global__ void k_dw4(int sel, int H, int W,
                      const float* __restrict__ wgt,
                      const float* __restrict__ sc,
                      const float* __restrict__ bi){
    const float* x = pick_x(sel);
    int q  = threadIdx.x & 63;
    int c0 = q*4;
    float wr[9][4];
    #pragma unroll
    for (int tp = 0; tp < 9; ++tp)
        #pragma unroll
        for (int j = 0; j < 4; ++j) wr[tp][j] = wgt[(c0+j)*9 + tp];
    float4 s4 = *(const float4*)(sc + c0);
    float4 b4 = *(const float4*)(bi + c0);
    int n = blockIdx.y;
    int HW = H*W;
    int lane = threadIdx.x >> 6;   // 0..3 pixel slots
    for (int hw = blockIdx.x*4 + lane; hw < HW; hw += gridDim.x*4){
        int w = hw % W, h = hw / W;
        float4 acc = make_float4(0,0,0,0);
        #pragma unroll
        for (int dy = 0; dy < 3; ++dy){
            int yy = h + dy - 1;
            if (yy < 0 || yy >= H) continue;
            #pragma unroll
            for (int dx = 0; dx < 3; ++dx){
                int xx = w + dx - 1;
                if (xx < 0 || xx >= W) continue;
                float4 v = *(const float4*)(x + ((size_t)(n*H+yy)*W + xx)*CH + c0);
                int tp = dy*3 + dx;
                acc.x += v.x*wr[tp][0]; acc.y += v.y*wr[tp][1];
                acc.z += v.z*wr[tp][2]; acc.w += v.w*wr[tp][3];
            }
        }
        float4 o;
        float t0 = acc.x*s4.x + b4.x; o.x = t0/(1.f+expf(-t0));
        float t1 = acc.y*s4.y + b4.y; o.y = t1/(1.f+expf(-t1));
        float t2 = acc.z*s4.z + b4.z; o.z = t2/(1.f+expf(-t2));
        float t3 = acc.w*s4.w + b4.w; o.w = t3/(1.f+expf(-t3));
        *(float4*)(g_dw + ((size_t)n*HW + hw)*CH + c0) = o;
    }
}

// ---------------- grouped conv 256->108, per-group blocks (high occupancy) ----
// blockIdx.y = group. patch = [64ch][PWP], wslab = [192][28]. ~34.8KB smem ->
// 6+ blocks/SM. thread = (li 0..6 -> 4 oc) x (pxq -> TPX pixels).
template<int STRIDE, int PXO, int TPX, int PXQ, int THREADS>
__global__ void __launch_bounds__(THREADS)
k_om3(int H, int W, int Ho, int Wo, const float* __restrict__ ob){
    constexpr int PW  = (PXO-1)*STRIDE + 3;
    constexpr int PWP = (PW + 3) & ~3;
    static_assert((TPX*STRIDE) % 4 == 0, "window alignment");
    extern __shared__ float sh[];
    float* patch = sh;              // [64][PWP]
    float* wsl   = sh + 64*PWP;     // [192][28]

    int nt   = (Wo + PXO - 1)/PXO;
    int g    = blockIdx.y;
    int b    = blockIdx.x;
    int tile = b % nt;
    int ho   = (b/nt) % Ho;
    int n    = b/(nt*Ho);
    int wo0  = tile*PXO;
    int hsrc = ho*STRIDE;
    int wsrc0= wo0*STRIDE;
    int cb   = g*64;

    int t   = threadIdx.x;
    int pxq = t % PXQ;
    int li  = t / PXQ;
    bool act = li < 7;
    int xb  = pxq*TPX*STRIDE;

    float4 acc[TPX];
    #pragma unroll
    for (int p = 0; p < TPX; ++p) acc[p] = make_float4(0,0,0,0);

    const float* wsrc_base = g_wT2 + g*28;
    for (int dy = 0; dy < 3; ++dy){
        __syncthreads();
        int gy = hsrc + dy - 1;
        for (int i = t; i < PW*64; i += THREADS){
            int c = i & 63, xx = i >> 6;
            int gx = wsrc0 + xx - 1;
            float v = 0.f;
            if (gy >= 0 && gy < H && gx >= 0 && gx < W)
                v = g_dw[((size_t)(n*H+gy)*W + gx)*CH + cb + c];
            patch[c*PWP + xx] = v;
        }
        {
            const float* src = wsrc_base + dy*192*112;
            for (int i = t; i < 192*7; i += THREADS){
                int row = i/7, col = (i%7)*4;
                *(float4*)(wsl + row*28 + col) = *(const float4*)(src + row*112 + col);
            }
        }
        __syncthreads();
        if (act){
            #pragma unroll 4
            for (int ic = 0; ic < 64; ++ic){
                const float* pr = patch + ic*PWP + xb;
                float f[8];
                *(float4*)(f)   = *(const float4*)(pr);
                *(float4*)(f+4) = *(const float4*)(pr+4);
                const float* wb = wsl + (ic*3)*28 + li*4;
                #pragma unroll
                for (int dx = 0; dx < 3; ++dx){
                    float4 wv = *(const float4*)(wb + dx*28);
                    #pragma unroll
                    for (int p = 0; p < TPX; ++p){
                        float s = f[dx + p*STRIDE];
                        acc[p].x += s*wv.x; acc[p].y += s*wv.y;
                        acc[p].z += s*wv.z; acc[p].w += s*wv.w;
                    }
                }
            }
        }
    }
    if (act){
        float bj[4];
        #pragma unroll
        for (int j = 0; j < 4; ++j){
            int jj = li*4 + j;
            bj[j] = (jj < 27) ? ob[g*27 + jj] : 0.f;
        }
        #pragma unroll
        for (int p = 0; p < TPX; ++p){
            int wo = wo0 + pxq*TPX + p;
            if (wo < Wo){
                size_t base = ((size_t)(n*Ho+ho)*Wo + wo)*OMC + g*27 + li*4;
                float av[4] = {acc[p].x, acc[p].y, acc[p].z, acc[p].w};
                #pragma unroll
                for (int j = 0; j < 4; ++j)
                    if (li*4 + j < 27) g_om[base + j] = av[j] + bj[j];
            }
        }
    }
}

// ---------------- DCNv3 sampler: geometry precomputed in smem ----------------
__global__ void k_samp5(int sel, int H, int W, int Ho, int Wo, int stride, int use_softmax){
    __shared__ float som[4][OMC];
    __shared__ float smk[4][36];
    __shared__ float sw[4][4][9][4];
    __shared__ int   soff[4][4][9][4];
    const float* x = pick_x(sel);
    int HW = Ho*Wo;
    int tiles = HW >> 2;
    int n  = blockIdx.x / tiles;
    int p0 = (blockIdx.x % tiles) * 4;
    int t  = threadIdx.x;

    for (int i = t; i < 4*OMC; i += 256)
        som[i/OMC][i%OMC] = g_om[((size_t)n*HW + p0 + i/OMC)*OMC + i%OMC];
    __syncthreads();

    if (use_softmax){
        if (t < 16){
            int pp = t >> 2, gg = t & 3;
            float mx = -1e30f;
            #pragma unroll
            for (int k = 0; k < 9; ++k) mx = fmaxf(mx, som[pp][72 + gg*9 + k]);
            float e[9], s = 0.f;
            #pragma unroll
            for (int k = 0; k < 9; ++k){ e[k] = expf(som[pp][72 + gg*9 + k] - mx); s += e[k]; }
            float inv = 1.f/s;
            #pragma unroll
            for (int k = 0; k < 9; ++k) smk[pp][gg*9 + k] = e[k]*inv;
        }
    } else {
        for (int i = t; i < 4*36; i += 256)
            smk[i/36][i%36] = 1.f/(1.f + expf(-som[i/36][72 + i%36]));
    }
    __syncthreads();

    // geometry: 144 threads = (pix 0..3, g 0..3, k 0..8)
    if (t < 144){
        int pix = t / 36, r = t % 36, gg = r / 9, k = r % 9;
        int hw = p0 + pix;
        int wo = hw % Wo, ho = hw / Wo;
        float py = (float)(ho*stride) + (float)(k/3 - 1) + som[pix][gg*18 + k*2];
        float px = (float)(wo*stride) + (float)(k%3 - 1) + som[pix][gg*18 + k*2 + 1];
        float m  = smk[pix][gg*9 + k];
        float fy = floorf(py), fx = floorf(px);
        float wy = py - fy, wx = px - fx;
        int iy = (int)fy, ix = (int)fx;
        #pragma unroll
        for (int d0 = 0; d0 < 2; ++d0){
            int yy = iy + d0;
            float wgy = d0 ? wy : (1.f - wy);
            #pragma unroll
            for (int d1 = 0; d1 < 2; ++d1){
                int xx = ix + d1;
                bool valid = (yy >= 0) & (yy < H) & (xx >= 0) & (xx < W);
                int yc = min(max(yy, 0), H-1);
                int xc = min(max(xx, 0), W-1);
                sw[pix][gg][k][d0*2+d1]  = valid ? wgy*(d1 ? wx : (1.f - wx))*m : 0.f;
                soff[pix][gg][k][d0*2+d1] = ((n*H + yc)*W + xc)*CH;
            }
        }
    }
    __syncthreads();

    int pix = t >> 6, q = t & 63, c0 = q*4, g = q >> 4;
    const float* xc = x + c0;
    float4 acc = make_float4(0,0,0,0);
    #pragma unroll
    for (int k = 0; k < 9; ++k){
        float4 wv = *(const float4*)&sw[pix][g][k][0];
        int4  ov = *(const int4*)&soff[pix][g][k][0];
        float4 v0 = *(const float4*)(xc + ov.x);
        float4 v1 = *(const float4*)(xc + ov.y);
        float4 v2 = *(const float4*)(xc + ov.z);
        float4 v3 = *(const float4*)(xc + ov.w);
        acc.x += wv.x*v0.x + wv.y*v1.x + wv.z*v2.x + wv.w*v3.x;
        acc.y += wv.x*v0.y + wv.y*v1.y + wv.z*v2.y + wv.w*v3.y;
        acc.z += wv.x*v0.z + wv.y*v1.z + wv.z*v2.z + wv.w*v3.z;
        acc.w += wv.x*v0.w + wv.y*v1.w + wv.z*v2.w + wv.w*v3.w;
    }
    *(float4*)(g_feat + ((size_t)n*HW + p0 + pix)*CH + c0) = acc;
}

// ---------------- fused stats (float4): GN mean/var + weighted channel means ----
__global__ void k_stats4(int Hs, int Ws, int Hup, int Wup, int ups, float normw){
    __shared__ float wy[80], wx[80];
    __shared__ float r1[256], r2[256];
    __shared__ float4 rw[256];
    int n = blockIdx.x >> 4, g = blockIdx.x & 15;
    int t = threadIdx.x;
    if (t == 0){
        if (ups){
            for (int i = 0; i < Hs; ++i) wy[i] = 0.f;
            for (int i = 0; i < Ws; ++i) wx[i] = 0.f;
            float ry = (Hup > 1) ? (float)(Hs-1)/(float)(Hup-1) : 0.f;
            float rx = (Wup > 1) ? (float)(Ws-1)/(float)(Wup-1) : 0.f;
            for (int j = 0; j < Hup; ++j){
                float c = j*ry; int i0 = (int)floorf(c); float f = c - (float)i0;
                wy[i0] += 1.f - f;
                if (i0 + 1 < Hs) wy[i0+1] += f;
            }
            for (int j = 0; j < Wup; ++j){
                float c = j*rx; int i0 = (int)floorf(c); float f = c - (float)i0;
                wx[i0] += 1.f - f;
                if (i0 + 1 < Ws) wx[i0+1] += f;
            }
        } else {
            for (int i = 0; i < Hs; ++i) wy[i] = 1.f;
            for (int i = 0; i < Ws; ++i) wx[i] = 1.f;
        }
    }
    __syncthreads();

    int HW = Hs*Ws;
    int q  = t & 3;
    int c0 = g*16 + q*4;
    float4 s4 = make_float4(0,0,0,0), w4 = make_float4(0,0,0,0);
    float ss = 0.f;
    int hw0 = t >> 2;
    int h = hw0 / Ws, w = hw0 % Ws;
    for (int hw = hw0; hw < HW; hw += 64){
        float4 v = *(const float4*)(g_feat + ((size_t)n*HW + hw)*CH + c0);
        s4.x += v.x; s4.y += v.y; s4.z += v.z; s4.w += v.w;
        ss += v.x*v.x + v.y*v.y + v.z*v.z + v.w*v.w;
        float ww = wy[h]*wx[w];
        w4.x += v.x*ww; w4.y += v.y*ww; w4.z += v.z*ww; w4.w += v.w*ww;
        w += 64; while (w >= Ws){ w -= Ws; ++h; }
    }
    r1[t] = s4.x + s4.y + s4.z + s4.w;
    r2[t] = ss;
    rw[t] = w4;
    __syncthreads();
    for (int o = 128; o >= 4; o >>= 1){
        if (t < o){
            r1[t] += r1[t+o]; r2[t] += r2[t+o];
            rw[t].x += rw[t+o].x; rw[t].y += rw[t+o].y;
            rw[t].z += rw[t+o].z; rw[t].w += rw[t+o].w;
        }
        __syncthreads();
    }
    if (t == 0){
        float s  = r1[0] + r1[1] + r1[2] + r1[3];
        float sq = r2[0] + r2[1] + r2[2] + r2[3];
        float cnt = (float)HW*16.f;
        float mu  = s/cnt;
        float var = sq/cnt - mu*mu;
        g_gmu[n*16 + g]  = mu;
        g_ginv[n*16 + g] = rsqrtf(var + 1e-5f);
    }
    if (t < 4){
        float4 wv = rw[t];
        int c = n*CH + g*16 + t*4;
        g_cmean[c]   = wv.x*normw; g_cmean[c+1] = wv.y*normw;
        g_cmean[c+2] = wv.z*normw; g_cmean[c+3] = wv.w*normw;
    }
}

// attn scalar + dyrelu pooled-mean accumulation
__global__ void k_attn2(int first, float invl,
                        const float* __restrict__ saw, const float* __restrict__ sab,
                        const float* __restrict__ gam, const float* __restrict__ bet){
    __shared__ float red[256];
    __shared__ float sa;
    int n = blockIdx.x, t = threadIdx.x;
    int g = t >> 4;
    float m = (g_cmean[n*CH + t] - g_gmu[n*16 + g])*g_ginv[n*16 + g]*gam[t] + bet[t];
    red[t] = m*saw[t];
    __syncthreads();
    for (int o = 128; o > 0; o >>= 1){
        if (t < o) red[t] += red[t+o];
        __syncthreads();
    }
    if (t == 0){
        float a = red[0] + sab[0];
        a = fmaxf(a, 0.f);
        a = fminf(fmaxf((a + 3.f)/6.f, 0.f), 1.f);
        sa = a; g_a[n] = a;
    }
    __syncthreads();
    float contrib = sa*m*invl;
    g_y[n*CH + t] = first ? contrib : (g_y[n*CH + t] + contrib);
}

// accumulate (no upsample), float4, GN + attn fused
__global__ void k_acc4(int HW, int first,
                       const float* __restrict__ gam, const float* __restrict__ bet){
    int n = blockIdx.y;
    int idx = blockIdx.x*256 + threadIdx.x;
    if (idx >= HW*64) return;
    int q = idx & 63, hw = idx >> 6;
    int c0 = q*4, g = q >> 2;
    float mu = g_gmu[n*16 + g], inv = g_ginv[n*16 + g], a = g_a[n];
    float4 v  = *(const float4*)(g_feat + ((size_t)n*HW + hw)*CH + c0);
    float4 g4 = *(const float4*)(gam + c0);
    float4 b4 = *(const float4*)(bet + c0);
    float4 r;
    r.x = a*((v.x - mu)*inv*g4.x + b4.x);
    r.y = a*((v.y - mu)*inv*g4.y + b4.y);
    r.z = a*((v.z - mu)*inv*g4.z + b4.z);
    r.w = a*((v.w - mu)*inv*g4.w + b4.w);
    float* dst = g_sum + ((size_t)n*HW + hw)*CH + c0;
    if (first) *(float4*)dst = r;
    else {
        float4 o = *(const float4*)dst;
        o.x += r.x; o.y += r.y; o.z += r.z; o.w += r.w;
        *(float4*)dst = o;
    }
}

// accumulate with bilinear upsample, float4, GN + attn fused (never first)
__global__ void k_acc_up4(int Hs, int Ws, int Ho, int Wo,
                          const float* __restrict__ gam, const float* __restrict__ bet){
    int n = blockIdx.y;
    int HWo = Ho*Wo;
    int idx = blockIdx.x*256 + threadIdx.x;
    if (idx >= HWo*64) return;
    int q = idx & 63, hw = idx >> 6;
    int c0 = q*4, g = q >> 2;
    int w = hw % Wo, h = hw / Wo;
    float ry = (Ho > 1) ? (float)(Hs-1)/(float)(Ho-1) : 0.f;
    float rx = (Wo > 1) ? (float)(Ws-1)/(float)(Wo-1) : 0.f;
    float cy = h*ry, cx = w*rx;
    int y0 = (int)floorf(cy), x0 = (int)floorf(cx);
    int y1 = min(y0+1, Hs-1), x1 = min(x0+1, Ws-1);
    float wyf = cy - (float)y0, wxf = cx - (float)x0;
    const float* f = g_feat;
    float4 v00 = *(const float4*)(f + ((size_t)(n*Hs+y0)*Ws + x0)*CH + c0);
    float4 v01 = *(const float4*)(f + ((size_t)(n*Hs+y0)*Ws + x1)*CH + c0);
    float4 v10 = *(const float4*)(f + ((size_t)(n*Hs+y1)*Ws + x0)*CH + c0);
    float4 v11 = *(const float4*)(f + ((size_t)(n*Hs+y1)*Ws + x1)*CH + c0);
    float a0 = (1.f-wyf)*(1.f-wxf), a1 = (1.f-wyf)*wxf, a2 = wyf*(1.f-wxf), a3 = wyf*wxf;
    float4 raw;
    raw.x = v00.x*a0 + v01.x*a1 + v10.x*a2 + v11.x*a3;
    raw.y = v00.y*a0 + v01.y*a1 + v10.y*a2 + v11.y*a3;
    raw.z = v00.z*a0 + v01.z*a1 + v10.z*a2 + v11.z*a3;
    raw.w = v00.w*a0 + v01.w*a1 + v10.w*a2 + v11.w*a3;
    float mu = g_gmu[n*16 + g], inv = g_ginv[n*16 + g], a = g_a[n];
    float4 g4 = *(const float4*)(gam + c0);
    float4 b4 = *(const float4*)(bet + c0);
    float* dst = g_sum + ((size_t)n*HWo + hw)*CH + c0;
    float4 o = *(const float4*)dst;
    o.x += a*((raw.x - mu)*inv*g4.x + b4.x);
    o.y += a*((raw.y - mu)*inv*g4.y + b4.y);
    o.z += a*((raw.z - mu)*inv*g4.z + b4.z);
    o.w += a*((raw.w - mu)*inv*g4.w + b4.w);
    *(float4*)dst = o;
}

// merged fc1+fc2 (dyrelu coefficients)
__global__ void k_fc(const float* __restrict__ w1, const float* __restrict__ b1,
                     const float* __restrict__ w2, const float* __restrict__ b2){
    __shared__ float h[4][64];
    int t = threadIdx.x;
    int n = t >> 6, j = t & 63;
    float s = b1[j];
    const float* wr = w1 + j*CH;
    for (int c = 0; c < CH; ++c) s += g_y[n*CH + c]*wr[c];
    h[n][j] = fmaxf(s, 0.f);
    __syncthreads();
    for (int og = t; og < NB*1024; og += 256){
        int nn = og >> 10, o = og & 1023;
        float s2 = b2[o];
        const float* w2r = w2 + o*64;
        #pragma unroll 16
        for (int j2 = 0; j2 < 64; ++j2) s2 += h[nn][j2]*w2r[j2];
        float z = fminf(fmaxf(s2 + 3.f, 0.f), 6.f)*(1.f/6.f);
        int qd = o >> 8;
        float v;
        if      (qd == 0) v = (z - 0.5f)*2.f + 1.f;
        else if (qd == 2) v = (z - 0.5f)*2.f;
        else              v = z - 0.5f;
        g_z[og] = v;
    }
}

// dyrelu + NHWC->NCHW tiled transposed write
__global__ void k_out2(int HW, float invl, float* __restrict__ out){
    __shared__ float tile[32][33];
    int n   = blockIdx.z;
    int hw0 = blockIdx.x*32;
    int c0  = blockIdx.y*32;
    int tx = threadIdx.x, ty = threadIdx.y;
    #pragma unroll
    for (int q = 0; q < 4; ++q){
        int hw = hw0 + ty + q*8;
        float v = (hw < HW) ? g_sum[((size_t)n*HW + hw)*CH + c0 + tx] : 0.f;
        tile[ty + q*8][tx] = v;
    }
    __syncthreads();
    int hw = hw0 + tx;
    if (hw < HW){
        #pragma unroll
        for (int q = 0; q < 4; ++q){
            int cl = ty + q*8;
            int c  = c0 + cl;
            float f  = tile[tx][cl]*invl;
            float a1 = g_z[n*1024 + c];
            float b1 = g_z[n*1024 + 256 + c];
            float a2 = g_z[n*1024 + 512 + c];
            float b2 = g_z[n*1024 + 768 + c];
            out[((size_t)n*CH + c)*HW + hw] = fmaxf(f*a1 + b1, f*a2 + b2);
        }
    }
}

// ---------------- host ----------------
extern "C" void kernel_launch(void* const* d_in, const int* in_sizes, int n_in,
                              void* d_out, int out_size){
    const float* x0     = (const float*)d_in[0];
    const float* x1     = (const float*)d_in[1];
    const float* x2     = (const float*)d_in[2];
    const float* dw_w_h = (const float*)d_in[3];
    const float* dw_s_h = (const float*)d_in[4];
    const float* dw_b_h = (const float*)d_in[5];
    const float* dw_w_m = (const float*)d_in[6];
    const float* dw_s_m = (const float*)d_in[7];
    const float* dw_b_m = (const float*)d_in[8];
    const float* dw_w_l = (const float*)d_in[9];
    const float* dw_s_l = (const float*)d_in[10];
    const float* dw_b_l = (const float*)d_in[11];
    const float* off_w  = (const float*)d_in[12];
    const float* off_b  = (const float*)d_in[13];
    const float* gn_g_h = (const float*)d_in[14];
    const float* gn_b_h = (const float*)d_in[15];
    const float* gn_g_m = (const float*)d_in[16];
    const float* gn_b_m = (const float*)d_in[17];
    const float* gn_g_l = (const float*)d_in[18];
    const float* gn_b_l = (const float*)d_in[19];
    const float* sa_w   = (const float*)d_in[20];
    const float* sa_b   = (const float*)d_in[21];
    const float* fc1_w  = (const float*)d_in[22];
    const float* fc1_b  = (const float*)d_in[23];
    const float* fc2_w  = (const float*)d_in[24];
    const float* fc2_b  = (const float*)d_in[25];
    float* out = (float*)d_out;

    auto dw = [&](int sel, int H, int W, const float* ww, const float* ss, const float* bb){
        int HW = H*W;
        int grid = (HW + 31)/32;
        k_dw4<<<dim3(grid, NB), 256>>>(sel, H, W, ww, ss, bb);
    };
    auto om = [&](int H, int W, int Ho, int Wo, int stride){
        if (stride == 1){
            if (Wo == 80){
                const int SM = (64*52 + 192*28)*4;
                k_om3<1,48,4,12,96><<<dim3(2*Ho*NB, 4), 96, SM>>>(H, W, Ho, Wo, off_b);
            } else if (Wo == 40){
                const int SM = (64*44 + 192*28)*4;
                k_om3<1,40,4,10,80><<<dim3(1*Ho*NB, 4), 80, SM>>>(H, W, Ho, Wo, off_b);
            } else {
                const int SM = (64*24 + 192*28)*4;
                k_om3<1,20,4,5,64><<<dim3(1*Ho*NB, 4), 64, SM>>>(H, W, Ho, Wo, off_b);
            }
        } else {
            const int SM = (64*44 + 192*28)*4;
            int nt = (Wo + 19)/20;
            k_om3<2,20,2,10,80><<<dim3(nt*Ho*NB, 4), 80, SM>>>(H, W, Ho, Wo, off_b);
        }
    };
    auto tail = [&](int sel, int Hs, int Ws, int Ho, int Wo, int stride, int softmax,
                    int upHo, int upWo, int first, float invl,
                    const float* gng, const float* gnb){
        k_samp5<<<NB*(Ho*Wo/4), 256>>>(sel, Hs, Ws, Ho, Wo, stride, softmax);
        if (upHo)
            k_stats4<<<NB*16, 256>>>(Ho, Wo, upHo, upWo, 1, 1.f/((float)upHo*(float)upWo));
        else
            k_stats4<<<NB*16, 256>>>(Ho, Wo, 0, 0, 0, 1.f/((float)Ho*(float)Wo));
        k_attn2<<<NB, 256>>>(first, invl, sa_w, sa_b, gng, gnb);
        if (upHo)
            k_acc_up4<<<dim3(upHo*upWo/4, NB), 256>>>(Ho, Wo, upHo, upWo, gng, gnb);
        else
            k_acc4<<<dim3(Ho*Wo/4, NB), 256>>>(Ho*Wo, first, gng, gnb);
    };
    auto finish = [&](int Ho, int Wo, int nlvls, float* optr){
        float invl = 1.f/(float)nlvls;
        k_fc<<<1, 256>>>(fc1_w, fc1_b, fc2_w, fc2_b);
        int HW = Ho*Wo;
        k_out2<<<dim3((HW+31)/32, 8, NB), dim3(32,8)>>>(HW, invl, optr);
    };

    // ---- level 0 mid branch first so ncu (-s 5) profiles k_om3 ----
    k_tr2<<<dim3(200, 8, NB), dim3(32,8)>>>(x0, 0, 6400);            // 0
    dw(0, 80, 80, dw_w_m, dw_s_m, dw_b_m);                           // 1
    k_wt2<<<(3*192*112 + 255)/256, 256>>>(off_w);                    // 2
    om(80, 80, 80, 80, 1);                                           // 3 <- profiled
    tail(0, 80, 80, 80, 80, 1, 0, 0, 0, 1, 0.5f, gn_g_m, gn_b_m);

    k_tr2<<<dim3(50, 8, NB), dim3(32,8)>>>(x1, 1, 1600);
    k_tr2<<<dim3(13, 8, NB), dim3(32,8)>>>(x2, 2,  400);

    // level 0 high: x1 -> 40x40 -> up 80x80
    dw(1, 40, 40, dw_w_h, dw_s_h, dw_b_h);
    om(40, 40, 40, 40, 1);
    tail(1, 40, 40, 40, 40, 1, 1, 80, 80, 0, 0.5f, gn_g_h, gn_b_h);
    finish(80, 80, 2, out);

    // level 1: mid(x1) + low(x0,s2) + high(x2 -> up 40)
    dw(1, 40, 40, dw_w_m, dw_s_m, dw_b_m);
    om(40, 40, 40, 40, 1);
    tail(1, 40, 40, 40, 40, 1, 0, 0, 0, 1, 1.f/3.f, gn_g_m, gn_b_m);

    dw(0, 80, 80, dw_w_l, dw_s_l, dw_b_l);
    om(80, 80, 40, 40, 2);
    tail(0, 80, 80, 40, 40, 2, 1, 0, 0, 0, 1.f/3.f, gn_g_l, gn_b_l);

    dw(2, 20, 20, dw_w_h, dw_s_h, dw_b_h);
    om(20, 20, 20, 20, 1);
    tail(2, 20, 20, 20, 20, 1, 1, 40, 40, 0, 1.f/3.f, gn_g_h, gn_b_h);
    finish(40, 40, 3, out + (size_t)NB*CH*80*80);

    // level 2: mid(x2) + low(x1,s2)
    dw(2, 20, 20, dw_w_m, dw_s_m, dw_b_m);
    om(20, 20, 20, 20, 1);
    tail(2, 20, 20, 20, 20, 1, 0, 0, 0, 1, 0.5f, gn_g_m, gn_b_m);

    dw(1, 40, 40, dw_w_l, dw_s_l, dw_b_l);
    om(40, 40, 20, 20, 2);
    tail(1, 40, 40, 20, 20, 2, 1, 0, 0, 0, 0.5f, gn_g_l, gn_b_l);
    finish(20, 20, 2, out + (size_t)NB*CH*80*80 + (size_t)NB*CH*40*40);
}

// round 5
// speedup vs baseline: 7.9408x; 1.5588x over previous
#include <cuda_runtime.h>
#include <math.h>

#define NB   4
#define CH   256
#define OMC  108

// ---- branch tables (7 branches) ----
// b0: lvl0 mid  x0 80 s1 -> 80      b1: lvl0 high x1 40 s1 -> 40 up80
// b2: lvl1 mid  x1 40 s1 -> 40      b3: lvl1 low  x0 80 s2 -> 40
// b4: lvl1 high x2 20 s1 -> 20 up40 b5: lvl2 mid  x2 20 s1 -> 20
// b6: lvl2 low  x1 40 s2 -> 20
__device__ __constant__ int BR_SRC[7]    = {0,1,1,0,2,2,1};
__device__ __constant__ int BR_HS[7]     = {80,40,40,80,20,20,40};
__device__ __constant__ int BR_STRIDE[7] = {1,1,1,2,1,1,2};
__device__ __constant__ int BR_HO[7]     = {80,40,40,40,20,20,20};
__device__ __constant__ int BR_SOFT[7]   = {0,1,0,1,1,0,1};
__device__ __constant__ int BR_UPH[7]    = {0,80,0,0,40,0,0};
__device__ __constant__ int BR_DWSEL[7]  = {0,1,0,2,1,0,2};   // 0=m,1=h,2=l
__device__ __constant__ int BR_GNSEL[7]  = {0,1,0,2,1,0,2};
__device__ __constant__ int DWPFX[7]     = {0,6400,8000,9600,16000,16400,16800}; // src px prefix
__device__ __constant__ int OMPFX[7]     = {0,6400,8000,9600,11200,11600,12000}; // out px prefix
__device__ __constant__ int SAMP_PFX[7]  = {0,1600,2000,2400,2800,2900,3000};    // out px/4 prefix

// ---------------- scratch ----------------
__device__ float g_x0[NB*80*80*CH];
__device__ float g_x1[NB*40*40*CH];
__device__ float g_x2[NB*20*20*CH];
__device__ float g_dwb[18400*NB*CH];
__device__ float g_om [12400*NB*OMC];
__device__ float g_feat[12400*NB*CH];
__device__ float g_sum[8800*NB*CH];        // lvl px prefix {0,6400,8000}
__device__ float g_wT2[3*192*112];
__device__ float g_a[7*NB];
__device__ float g_y[3*NB*CH];
__device__ float g_z[3*NB*1024];
__device__ float g_cmean[7*NB*CH];
__device__ float g_gmu[7*NB*16];
__device__ float g_ginv[7*NB*16];

__device__ __forceinline__ const float* pick_x(int s){
    return s==0 ? g_x0 : (s==1 ? g_x1 : g_x2);
}
__device__ __forceinline__ float* pick_xm(int s){
    return s==0 ? g_x0 : (s==1 ? g_x1 : g_x2);
}

// ---------------- NCHW -> NHWC tiled transpose ----------------
__global__ void k_tr2(const float* __restrict__ in, int sel, int HW){
    __shared__ float tile[32][33];
    float* out = pick_xm(sel);
    int n  = blockIdx.z;
    int hw0 = blockIdx.x*32;
    int c0  = blockIdx.y*32;
    int tx = threadIdx.x, ty = threadIdx.y;
    #pragma unroll
    for (int q = 0; q < 4; ++q){
        int c = c0 + ty + q*8;
        int hw = hw0 + tx;
        float v = (hw < HW) ? in[((size_t)n*CH + c)*HW + hw] : 0.f;
        tile[ty + q*8][tx] = v;
    }
    __syncthreads();
    #pragma unroll
    for (int q = 0; q < 4; ++q){
        int hw = hw0 + ty + q*8;
        int c  = c0 + tx;
        if (hw < HW) out[((size_t)n*HW + hw)*CH + c] = tile[tx][ty + q*8];
    }
}

// weight transform: [dy][ic*3+dx][slot(4g x 28)]
__global__ void k_wt2(const float* __restrict__ ow){
    int i = blockIdx.x*blockDim.x + threadIdx.x;
    if (i >= 3*192*112) return;
    int slot = i % 112;
    int r    = (i / 112) % 192;
    int dy   = i / (112*192);
    int ic = r/3, dx = r%3;
    int g = slot/28, jj = slot%28;
    float v = 0.f;
    if (jj < 27) v = ow[(g*27+jj)*576 + ic*9 + dy*3 + dx];
    g_wT2[i] = v;
}

// ---------------- batched depthwise conv (all 7 branches) ----------------
__global__ void k_dwB(const float* __restrict__ wm, const float* __restrict__ sm_, const float* __restrict__ bm_,
                      const float* __restrict__ wh, const float* __restrict__ sh_, const float* __restrict__ bh_,
                      const float* __restrict__ wl, const float* __restrict__ sl_, const float* __restrict__ bl_){
    int b = blockIdx.y, n = blockIdx.z;
    int sel = BR_DWSEL[b];
    const float* wgt = sel==0 ? wm : (sel==1 ? wh : wl);
    const float* sc  = sel==0 ? sm_ : (sel==1 ? sh_ : sl_);
    const float* bi  = sel==0 ? bm_ : (sel==1 ? bh_ : bl_);
    const float* x = pick_x(BR_SRC[b]);
    int H = BR_HS[b], W = H, HW = H*W;
    float* dst = g_dwb + (size_t)DWPFX[b]*NB*CH;

    int q  = threadIdx.x & 63;
    int c0 = q*4;
    float wr[9][4];
    #pragma unroll
    for (int tp = 0; tp < 9; ++tp)
        #pragma unroll
        for (int j = 0; j < 4; ++j) wr[tp][j] = wgt[(c0+j)*9 + tp];
    float4 s4 = *(const float4*)(sc + c0);
    float4 b4 = *(const float4*)(bi + c0);
    int lane = threadIdx.x >> 6;
    for (int hw = blockIdx.x*4 + lane; hw < HW; hw += gridDim.x*4){
        int w = hw % W, h = hw / W;
        float4 acc = make_float4(0,0,0,0);
        #pragma unroll
        for (int dy = 0; dy < 3; ++dy){
            int yy = h + dy - 1;
            if (yy < 0 || yy >= H) continue;
            #pragma unroll
            for (int dx = 0; dx < 3; ++dx){
                int xx = w + dx - 1;
                if (xx < 0 || xx >= W) continue;
                float4 v = *(const float4*)(x + ((size_t)(n*H+yy)*W + xx)*CH + c0);
                int tp = dy*3 + dx;
                acc.x += v.x*wr[tp][0]; acc.y += v.y*wr[tp][1];
                acc.z += v.z*wr[tp][2]; acc.w += v.w*wr[tp][3];
            }
        }
        float4 o;
        float t0 = acc.x*s4.x + b4.x; o.x = t0/(1.f+expf(-t0));
        float t1 = acc.y*s4.y + b4.y; o.y = t1/(1.f+expf(-t1));
        float t2 = acc.z*s4.z + b4.z; o.z = t2/(1.f+expf(-t2));
        float t3 = acc.w*s4.w + b4.w; o.w = t3/(1.f+expf(-t3));
        *(float4*)(dst + ((size_t)n*HW + hw)*CH + c0) = o;
    }
}

// ---------------- grouped conv 256->108, per-group blocks, branch-batched ----
template<int STRIDE, int PXO, int TPX, int PXQ, int THREADS>
__global__ void __launch_bounds__(THREADS)
k_om3(int H, int W, int Ho, int Wo, const float* __restrict__ ob, int bA, int bB){
    constexpr int PW  = (PXO-1)*STRIDE + 3;
    constexpr int PWP = (PW + 3) & ~3;
    static_assert((TPX*STRIDE) % 4 == 0, "window alignment");
    extern __shared__ float sh[];
    float* patch = sh;              // [64][PWP]
    float* wsl   = sh + 64*PWP;     // [192][28]

    int br   = blockIdx.z == 0 ? bA : bB;
    const float* src = g_dwb + (size_t)DWPFX[br]*NB*CH;
    float* dst       = g_om  + (size_t)OMPFX[br]*NB*OMC;

    int nt   = (Wo + PXO - 1)/PXO;
    int g    = blockIdx.y;
    int b    = blockIdx.x;
    int tile = b % nt;
    int ho   = (b/nt) % Ho;
    int n    = b/(nt*Ho);
    int wo0  = tile*PXO;
    int hsrc = ho*STRIDE;
    int wsrc0= wo0*STRIDE;
    int cb   = g*64;

    int t   = threadIdx.x;
    int pxq = t % PXQ;
    int li  = t / PXQ;
    bool act = li < 7;
    int xb  = pxq*TPX*STRIDE;

    float4 acc[TPX];
    #pragma unroll
    for (int p = 0; p < TPX; ++p) acc[p] = make_float4(0,0,0,0);

    const float* wsrc_base = g_wT2 + g*28;
    for (int dy = 0; dy < 3; ++dy){
        __syncthreads();
        int gy = hsrc + dy - 1;
        for (int i = t; i < PW*64; i += THREADS){
            int c = i & 63, xx = i >> 6;
            int gx = wsrc0 + xx - 1;
            float v = 0.f;
            if (gy >= 0 && gy < H && gx >= 0 && gx < W)
                v = src[((size_t)(n*H+gy)*W + gx)*CH + cb + c];
            patch[c*PWP + xx] = v;
        }
        {
            const float* ws = wsrc_base + dy*192*112;
            for (int i = t; i < 192*7; i += THREADS){
                int row = i/7, col = (i%7)*4;
                *(float4*)(wsl + row*28 + col) = *(const float4*)(ws + row*112 + col);
            }
        }
        __syncthreads();
        if (act){
            #pragma unroll 4
            for (int ic = 0; ic < 64; ++ic){
                const float* pr = patch + ic*PWP + xb;
                float f[8];
                *(float4*)(f)   = *(const float4*)(pr);
                *(float4*)(f+4) = *(const float4*)(pr+4);
                const float* wb = wsl + (ic*3)*28 + li*4;
                #pragma unroll
                for (int dx = 0; dx < 3; ++dx){
                    float4 wv = *(const float4*)(wb + dx*28);
                    #pragma unroll
                    for (int p = 0; p < TPX; ++p){
                        float s = f[dx + p*STRIDE];
                        acc[p].x += s*wv.x; acc[p].y += s*wv.y;
                        acc[p].z += s*wv.z; acc[p].w += s*wv.w;
                    }
                }
            }
        }
    }
    if (act){
        float bj[4];
        #pragma unroll
        for (int j = 0; j < 4; ++j){
            int jj = li*4 + j;
            bj[j] = (jj < 27) ? ob[g*27 + jj] : 0.f;
        }
        #pragma unroll
        for (int p = 0; p < TPX; ++p){
            int wo = wo0 + pxq*TPX + p;
            if (wo < Wo){
                size_t base = ((size_t)(n*Ho+ho)*Wo + wo)*OMC + g*27 + li*4;
                float av[4] = {acc[p].x, acc[p].y, acc[p].z, acc[p].w};
                #pragma unroll
                for (int j = 0; j < 4; ++j)
                    if (li*4 + j < 27) dst[base + j] = av[j] + bj[j];
            }
        }
    }
}

// ---------------- batched DCNv3 sampler ----------------
__global__ void k_sampB(){
    __shared__ float som[4][OMC];
    __shared__ float smk[4][36];
    __shared__ float sw[4][4][9][4];
    __shared__ int   soff[4][4][9][4];
    int bx = blockIdx.x;
    int b = 0;
    #pragma unroll
    for (int i = 1; i < 7; ++i) if (bx >= SAMP_PFX[i]) b = i;
    int n = blockIdx.y;
    int p0 = (bx - SAMP_PFX[b])*4;
    int Ho = BR_HO[b], Wo = Ho, HW = Ho*Wo;
    int H  = BR_HS[b], W = H;
    int stride = BR_STRIDE[b];
    int use_softmax = BR_SOFT[b];
    const float* x = pick_x(BR_SRC[b]);
    const float* omp = g_om + ((size_t)OMPFX[b]*NB + (size_t)n*HW)*OMC;
    int t = threadIdx.x;

    for (int i = t; i < 4*OMC; i += 256)
        som[i/OMC][i%OMC] = omp[(size_t)(p0 + i/OMC)*OMC + i%OMC];
    __syncthreads();

    if (use_softmax){
        if (t < 16){
            int pp = t >> 2, gg = t & 3;
            float mx = -1e30f;
            #pragma unroll
            for (int k = 0; k < 9; ++k) mx = fmaxf(mx, som[pp][72 + gg*9 + k]);
            float e[9], s = 0.f;
            #pragma unroll
            for (int k = 0; k < 9; ++k){ e[k] = expf(som[pp][72 + gg*9 + k] - mx); s += e[k]; }
            float inv = 1.f/s;
            #pragma unroll
            for (int k = 0; k < 9; ++k) smk[pp][gg*9 + k] = e[k]*inv;
        }
    } else {
        for (int i = t; i < 4*36; i += 256)
            smk[i/36][i%36] = 1.f/(1.f + expf(-som[i/36][72 + i%36]));
    }
    __syncthreads();

    if (t < 144){
        int pix = t / 36, r = t % 36, gg = r / 9, k = r % 9;
        int hw = p0 + pix;
        int wo = hw % Wo, ho = hw / Wo;
        float py = (float)(ho*stride) + (float)(k/3 - 1) + som[pix][gg*18 + k*2];
        float px = (float)(wo*stride) + (float)(k%3 - 1) + som[pix][gg*18 + k*2 + 1];
        float m  = smk[pix][gg*9 + k];
        float fy = floorf(py), fx = floorf(px);
        float wy = py - fy, wx = px - fx;
        int iy = (int)fy, ix = (int)fx;
        #pragma unroll
        for (int d0 = 0; d0 < 2; ++d0){
            int yy = iy + d0;
            float wgy = d0 ? wy : (1.f - wy);
            #pragma unroll
            for (int d1 = 0; d1 < 2; ++d1){
                int xx = ix + d1;
                bool valid = (yy >= 0) & (yy < H) & (xx >= 0) & (xx < W);
                int yc = min(max(yy, 0), H-1);
                int xc = min(max(xx, 0), W-1);
                sw[pix][gg][k][d0*2+d1]   = valid ? wgy*(d1 ? wx : (1.f - wx))*m : 0.f;
                soff[pix][gg][k][d0*2+d1] = ((n*H + yc)*W + xc)*CH;
            }
        }
    }
    __syncthreads();

    int pix = t >> 6, q = t & 63, c0 = q*4, g = q >> 4;
    const float* xc = x + c0;
    float4 acc = make_float4(0,0,0,0);
    #pragma unroll
    for (int k = 0; k < 9; ++k){
        float4 wv = *(const float4*)&sw[pix][g][k][0];
        int4  ov = *(const int4*)&soff[pix][g][k][0];
        float4 v0 = *(const float4*)(xc + ov.x);
        float4 v1 = *(const float4*)(xc + ov.y);
        float4 v2 = *(const float4*)(xc + ov.z);
        float4 v3 = *(const float4*)(xc + ov.w);
        acc.x += wv.x*v0.x + wv.y*v1.x + wv.z*v2.x + wv.w*v3.x;
        acc.y += wv.x*v0.y + wv.y*v1.y + wv.z*v2.y + wv.w*v3.y;
        acc.z += wv.x*v0.z + wv.y*v1.z + wv.z*v2.z + wv.w*v3.z;
        acc.w += wv.x*v0.w + wv.y*v1.w + wv.z*v2.w + wv.w*v3.w;
    }
    *(float4*)(g_feat + ((size_t)OMPFX[b]*NB + (size_t)n*HW + p0 + pix)*CH + c0) = acc;
}

// ---------------- batched stats: GN mean/var + weighted channel means --------
__global__ void k_statsB(){
    __shared__ float wy[80], wx[80];
    __shared__ float r1[256], r2[256];
    __shared__ float4 rw[256];
    int b = blockIdx.x >> 4, g = blockIdx.x & 15, n = blockIdx.y;
    int Hs = BR_HO[b], Ws = Hs, HW = Hs*Ws;
    int uph = BR_UPH[b];
    float normw = uph ? 1.f/((float)uph*(float)uph) : 1.f/(float)HW;
    int t = threadIdx.x;
    if (t == 0){
        if (uph){
            for (int i = 0; i < Hs; ++i){ wy[i] = 0.f; wx[i] = 0.f; }
            float ry = (float)(Hs-1)/(float)(uph-1);
            for (int j = 0; j < uph; ++j){
                float c = j*ry; int i0 = (int)floorf(c); float f = c - (float)i0;
                wy[i0] += 1.f - f;
                if (i0 + 1 < Hs) wy[i0+1] += f;
            }
            for (int i = 0; i < Hs; ++i) wx[i] = wy[i];
        } else {
            for (int i = 0; i < Hs; ++i){ wy[i] = 1.f; wx[i] = 1.f; }
        }
    }
    __syncthreads();

    const float* fb = g_feat + ((size_t)OMPFX[b]*NB + (size_t)n*HW)*CH;
    int q  = t & 3;
    int c0 = g*16 + q*4;
    float4 s4 = make_float4(0,0,0,0), w4 = make_float4(0,0,0,0);
    float ss = 0.f;
    int hw0 = t >> 2;
    int h = hw0 / Ws, w = hw0 % Ws;
    for (int hw = hw0; hw < HW; hw += 64){
        float4 v = *(const float4*)(fb + (size_t)hw*CH + c0);
        s4.x += v.x; s4.y += v.y; s4.z += v.z; s4.w += v.w;
        ss += v.x*v.x + v.y*v.y + v.z*v.z + v.w*v.w;
        float ww = wy[h]*wx[w];
        w4.x += v.x*ww; w4.y += v.y*ww; w4.z += v.z*ww; w4.w += v.w*ww;
        w += 64; while (w >= Ws){ w -= Ws; ++h; }
    }
    r1[t] = s4.x + s4.y + s4.z + s4.w;
    r2[t] = ss;
    rw[t] = w4;
    __syncthreads();
    for (int o = 128; o >= 4; o >>= 1){
        if (t < o){
            r1[t] += r1[t+o]; r2[t] += r2[t+o];
            rw[t].x += rw[t+o].x; rw[t].y += rw[t+o].y;
            rw[t].z += rw[t+o].z; rw[t].w += rw[t+o].w;
        }
        __syncthreads();
    }
    if (t == 0){
        float s  = r1[0] + r1[1] + r1[2] + r1[3];
        float sq = r2[0] + r2[1] + r2[2] + r2[3];
        float cnt = (float)HW*16.f;
        float mu  = s/cnt;
        float var = sq/cnt - mu*mu;
        g_gmu [(b*NB+n)*16 + g] = mu;
        g_ginv[(b*NB+n)*16 + g] = rsqrtf(var + 1e-5f);
    }
    if (t < 4){
        float4 wv = rw[t];
        int c = (b*NB+n)*CH + g*16 + t*4;
        g_cmean[c]   = wv.x*normw; g_cmean[c+1] = wv.y*normw;
        g_cmean[c+2] = wv.z*normw; g_cmean[c+3] = wv.w*normw;
    }
}

// ---------------- attn scalars + pooled means, all levels ----------------
__device__ __constant__ int LVL_NBR[3] = {2,3,2};
__device__ __constant__ int LVL_BRS[3][3] = {{0,1,-1},{2,3,4},{5,6,-1}};

__global__ void k_attnB(const float* __restrict__ saw, const float* __restrict__ sab,
                        const float* __restrict__ gm, const float* __restrict__ bm,
                        const float* __restrict__ gh, const float* __restrict__ bh,
                        const float* __restrict__ gl, const float* __restrict__ bl){
    __shared__ float red[256];
    __shared__ float sa;
    int lvl = blockIdx.x, n = blockIdx.y, t = threadIdx.x;
    int g = t >> 4;
    int nbr = LVL_NBR[lvl];
    float invl = 1.f/(float)nbr;
    float y = 0.f;
    for (int i = 0; i < nbr; ++i){
        int b = LVL_BRS[lvl][i];
        int gs = BR_GNSEL[b];
        const float* gam = gs==0 ? gm : (gs==1 ? gh : gl);
        const float* bet = gs==0 ? bm : (gs==1 ? bh : bl);
        float m = (g_cmean[(b*NB+n)*CH + t] - g_gmu[(b*NB+n)*16 + g])
                  * g_ginv[(b*NB+n)*16 + g] * gam[t] + bet[t];
        red[t] = m*saw[t];
        __syncthreads();
        for (int o = 128; o > 0; o >>= 1){
            if (t < o) red[t] += red[t+o];
            __syncthreads();
        }
        if (t == 0){
            float a = red[0] + sab[0];
            a = fmaxf(a, 0.f);
            a = fminf(fmaxf((a + 3.f)/6.f, 0.f), 1.f);
            sa = a; g_a[b*NB + n] = a;
        }
        __syncthreads();
        y += sa*m*invl;
        __syncthreads();
    }
    g_y[(lvl*NB + n)*CH + t] = y;
}

// ---------------- per-level fused accumulate (GN + attn + upsample + sum) ----
__device__ __forceinline__ float4 feat_rd(int b, int n, int HW, int hw, int c0){
    return *(const float4*)(g_feat + ((size_t)OMPFX[b]*NB + (size_t)n*HW + hw)*CH + c0);
}
__device__ __forceinline__ float4 feat_up(int b, int n, int Hs, int Ho, int h, int w, int c0){
    float r = (float)(Hs-1)/(float)(Ho-1);
    float cy = h*r, cx = w*r;
    int y0 = (int)floorf(cy), x0 = (int)floorf(cx);
    int y1 = min(y0+1, Hs-1), x1 = min(x0+1, Hs-1);
    float wyf = cy - (float)y0, wxf = cx - (float)x0;
    const float* fb = g_feat + ((size_t)OMPFX[b]*NB + (size_t)n*Hs*Hs)*CH + c0;
    float4 v00 = *(const float4*)(fb + (size_t)(y0*Hs + x0)*CH);
    float4 v01 = *(const float4*)(fb + (size_t)(y0*Hs + x1)*CH);
    float4 v10 = *(const float4*)(fb + (size_t)(y1*Hs + x0)*CH);
    float4 v11 = *(const float4*)(fb + (size_t)(y1*Hs + x1)*CH);
    float a0 = (1.f-wyf)*(1.f-wxf), a1 = (1.f-wyf)*wxf, a2 = wyf*(1.f-wxf), a3 = wyf*wxf;
    float4 o;
    o.x = v00.x*a0 + v01.x*a1 + v10.x*a2 + v11.x*a3;
    o.y = v00.y*a0 + v01.y*a1 + v10.y*a2 + v11.y*a3;
    o.z = v00.z*a0 + v01.z*a1 + v10.z*a2 + v11.z*a3;
    o.w = v00.w*a0 + v01.w*a1 + v10.w*a2 + v11.w*a3;
    return o;
}
__device__ __forceinline__ void gn_acc(float4& o, float4 raw, int b, int n, int g, int c0,
                                       const float* gam, const float* bet){
    float mu = g_gmu[(b*NB+n)*16 + g], inv = g_ginv[(b*NB+n)*16 + g], a = g_a[b*NB + n];
    float4 g4 = *(const float4*)(gam + c0);
    float4 b4 = *(const float4*)(bet + c0);
    o.x += a*((raw.x - mu)*inv*g4.x + b4.x);
    o.y += a*((raw.y - mu)*inv*g4.y + b4.y);
    o.z += a*((raw.z - mu)*inv*g4.z + b4.z);
    o.w += a*((raw.w - mu)*inv*g4.w + b4.w);
}

template<int LVL>
__global__ void k_accL(const float* __restrict__ gm, const float* __restrict__ bm,
                       const float* __restrict__ gh, const float* __restrict__ bh,
                       const float* __restrict__ gl, const float* __restrict__ bl){
    constexpr int HoL = (LVL==0) ? 80 : (LVL==1 ? 40 : 20);
    constexpr int HWL = HoL*HoL;
    constexpr int SUMP = (LVL==0) ? 0 : (LVL==1 ? 6400 : 8000);
    int n = blockIdx.y;
    int idx = blockIdx.x*256 + threadIdx.x;
    if (idx >= HWL*64) return;
    int q = idx & 63, hw = idx >> 6;
    int c0 = q*4, g = q >> 2;
    int w = hw % HoL, h = hw / HoL;
    float4 o = make_float4(0,0,0,0);
    if (LVL == 0){
        gn_acc(o, feat_rd(0, n, 6400, hw, c0), 0, n, g, c0, gm, bm);
        gn_acc(o, feat_up(1, n, 40, 80, h, w, c0), 1, n, g, c0, gh, bh);
    } else if (LVL == 1){
        gn_acc(o, feat_rd(2, n, 1600, hw, c0), 2, n, g, c0, gm, bm);
        gn_acc(o, feat_rd(3, n, 1600, hw, c0), 3, n, g, c0, gl, bl);
        gn_acc(o, feat_up(4, n, 20, 40, h, w, c0), 4, n, g, c0, gh, bh);
    } else {
        gn_acc(o, feat_rd(5, n, 400, hw, c0), 5, n, g, c0, gm, bm);
        gn_acc(o, feat_rd(6, n, 400, hw, c0), 6, n, g, c0, gl, bl);
    }
    *(float4*)(g_sum + ((size_t)SUMP*NB + (size_t)n*HWL + hw)*CH + c0) = o;
}

// ---------------- fc (all levels) ----------------
__global__ void k_fcB(const float* __restrict__ w1, const float* __restrict__ b1,
                      const float* __restrict__ w2, const float* __restrict__ b2){
    __shared__ float h[4][64];
    int lvl = blockIdx.x;
    int t = threadIdx.x;
    int n = t >> 6, j = t & 63;
    float s = b1[j];
    const float* wr = w1 + j*CH;
    const float* yv = g_y + (lvl*NB + n)*CH;
    for (int c = 0; c < CH; ++c) s += yv[c]*wr[c];
    h[n][j] = fmaxf(s, 0.f);
    __syncthreads();
    for (int og = t; og < NB*1024; og += 256){
        int nn = og >> 10, o = og & 1023;
        float s2 = b2[o];
        const float* w2r = w2 + o*64;
        #pragma unroll 16
        for (int j2 = 0; j2 < 64; ++j2) s2 += h[nn][j2]*w2r[j2];
        float z = fminf(fmaxf(s2 + 3.f, 0.f), 6.f)*(1.f/6.f);
        int qd = o >> 8;
        float v;
        if      (qd == 0) v = (z - 0.5f)*2.f + 1.f;
        else if (qd == 2) v = (z - 0.5f)*2.f;
        else              v = z - 0.5f;
        g_z[(lvl*NB + nn)*1024 + o] = v;
    }
}

// ---------------- dyrelu + NHWC->NCHW output ----------------
__global__ void k_out2(int HW, float invl, float* __restrict__ out, int sump, int lvl){
    __shared__ float tile[32][33];
    int n   = blockIdx.z;
    int hw0 = blockIdx.x*32;
    int c0  = blockIdx.y*32;
    int tx = threadIdx.x, ty = threadIdx.y;
    const float* sb = g_sum + ((size_t)sump*NB + (size_t)n*HW)*CH;
    #pragma unroll
    for (int q = 0; q < 4; ++q){
        int hw = hw0 + ty + q*8;
        float v = (hw < HW) ? sb[(size_t)hw*CH + c0 + tx] : 0.f;
        tile[ty + q*8][tx] = v;
    }
    __syncthreads();
    int hw = hw0 + tx;
    if (hw < HW){
        const float* zb = g_z + (lvl*NB + n)*1024;
        #pragma unroll
        for (int q = 0; q < 4; ++q){
            int cl = ty + q*8;
            int c  = c0 + cl;
            float f  = tile[tx][cl]*invl;
            float a1 = zb[c];
            float b1 = zb[256 + c];
            float a2 = zb[512 + c];
            float b2 = zb[768 + c];
            out[((size_t)n*CH + c)*HW + hw] = fmaxf(f*a1 + b1, f*a2 + b2);
        }
    }
}

// ---------------- host ----------------
extern "C" void kernel_launch(void* const* d_in, const int* in_sizes, int n_in,
                              void* d_out, int out_size){
    const float* x0     = (const float*)d_in[0];
    const float* x1     = (const float*)d_in[1];
    const float* x2     = (const float*)d_in[2];
    const float* dw_w_h = (const float*)d_in[3];
    const float* dw_s_h = (const float*)d_in[4];
    const float* dw_b_h = (const float*)d_in[5];
    const float* dw_w_m = (const float*)d_in[6];
    const float* dw_s_m = (const float*)d_in[7];
    const float* dw_b_m = (const float*)d_in[8];
    const float* dw_w_l = (const float*)d_in[9];
    const float* dw_s_l = (const float*)d_in[10];
    const float* dw_b_l = (const float*)d_in[11];
    const float* off_w  = (const float*)d_in[12];
    const float* off_b  = (const float*)d_in[13];
    const float* gn_g_h = (const float*)d_in[14];
    const float* gn_b_h = (const float*)d_in[15];
    const float* gn_g_m = (const float*)d_in[16];
    const float* gn_b_m = (const float*)d_in[17];
    const float* gn_g_l = (const float*)d_in[18];
    const float* gn_b_l = (const float*)d_in[19];
    const float* sa_w   = (const float*)d_in[20];
    const float* sa_b   = (const float*)d_in[21];
    const float* fc1_w  = (const float*)d_in[22];
    const float* fc1_b  = (const float*)d_in[23];
    const float* fc2_w  = (const float*)d_in[24];
    const float* fc2_b  = (const float*)d_in[25];
    float* out = (float*)d_out;

    // stage 1: layout transforms (ours #0..#2), then batched dw (#3 <- ncu)
    k_tr2<<<dim3(200, 8, NB), dim3(32,8)>>>(x0, 0, 6400);
    k_tr2<<<dim3(50,  8, NB), dim3(32,8)>>>(x1, 1, 1600);
    k_tr2<<<dim3(13,  8, NB), dim3(32,8)>>>(x2, 2,  400);
    k_dwB<<<dim3(200, 7, NB), 256>>>(dw_w_m, dw_s_m, dw_b_m,
                                     dw_w_h, dw_s_h, dw_b_h,
                                     dw_w_l, dw_s_l, dw_b_l);
    k_wt2<<<(3*192*112 + 255)/256, 256>>>(off_w);

    // stage 2: offset/mask convs (5 launches, shape-classed)
    {
        const int SM80 = (64*52 + 192*28)*4;
        k_om3<1,48,4,12,96><<<dim3(2*80*NB, 4, 1), 96, SM80>>>(80, 80, 80, 80, off_b, 0, 0);
        const int SM40 = (64*44 + 192*28)*4;
        k_om3<1,40,4,10,80><<<dim3(1*40*NB, 4, 2), 80, SM40>>>(40, 40, 40, 40, off_b, 1, 2);
        k_om3<2,20,2,10,80><<<dim3(2*40*NB, 4, 1), 80, SM40>>>(80, 80, 40, 40, off_b, 3, 3);
        const int SM20 = (64*24 + 192*28)*4;
        k_om3<1,20,4,5,64><<<dim3(1*20*NB, 4, 2), 64, SM20>>>(20, 20, 20, 20, off_b, 4, 5);
        k_om3<2,20,2,10,80><<<dim3(1*20*NB, 4, 1), 80, SM40>>>(40, 40, 20, 20, off_b, 6, 6);
    }

    // stage 3: sampling, stats, attn — one launch each
    k_sampB<<<dim3(3100, NB), 256>>>();
    k_statsB<<<dim3(7*16, NB), 256>>>();
    k_attnB<<<dim3(3, NB), 256>>>(sa_w, sa_b, gn_g_m, gn_b_m, gn_g_h, gn_b_h, gn_g_l, gn_b_l);

    // stage 4: fused per-level accumulate, fc, output
    k_accL<0><<<dim3(6400*64/256, NB), 256>>>(gn_g_m, gn_b_m, gn_g_h, gn_b_h, gn_g_l, gn_b_l);
    k_accL<1><<<dim3(1600*64/256, NB), 256>>>(gn_g_m, gn_b_m, gn_g_h, gn_b_h, gn_g_l, gn_b_l);
    k_accL<2><<<dim3( 400*64/256, NB), 256>>>(gn_g_m, gn_b_m, gn_g_h, gn_b_h, gn_g_l, gn_b_l);
    k_fcB<<<3, 256>>>(fc1_w, fc1_b, fc2_w, fc2_b);

    k_out2<<<dim3(200, 8, NB), dim3(32,8)>>>(6400, 0.5f,     out,                                         0,    0);
    k_out2<<<dim3(50,  8, NB), dim3(32,8)>>>(1600, 1.f/3.f,  out + (size_t)NB*CH*6400,                    6400, 1);
    k_out2<<<dim3(13,  8, NB), dim3(32,8)>>>(400,  0.5f,     out + (size_t)NB*CH*6400 + (size_t)NB*CH*1600, 8000, 2);
}

// round 6
// speedup vs baseline: 8.1104x; 1.0214x over previous
#include <cuda_runtime.h>
#include <math.h>

#define NB   4
#define CH   256
#define OMC  108

// ---- packed f32x2 ops (Blackwell FFMA2 — 2x fp32 FMA throughput) ----
#define PACKF2(out, lo, hi) \
    asm("mov.b64 %0, {%1, %2};" : "=l"(out) : "f"(lo), "f"(hi))
#define UNPACKF2(lo, hi, in) \
    asm("mov.b64 {%0, %1}, %2;" : "=f"(lo), "=f"(hi) : "l"(in))
#define FMAF2(d, a, b, c) \
    asm("fma.rn.f32x2 %0, %1, %2, %3;" : "=l"(d) : "l"(a), "l"(b), "l"(c))

// ---- branch tables (7 branches) ----
__device__ __constant__ int BR_SRC[7]    = {0,1,1,0,2,2,1};
__device__ __constant__ int BR_HS[7]     = {80,40,40,80,20,20,40};
__device__ __constant__ int BR_STRIDE[7] = {1,1,1,2,1,1,2};
__device__ __constant__ int BR_HO[7]     = {80,40,40,40,20,20,20};
__device__ __constant__ int BR_SOFT[7]   = {0,1,0,1,1,0,1};
__device__ __constant__ int BR_UPH[7]    = {0,80,0,0,40,0,0};
__device__ __constant__ int BR_DWSEL[7]  = {0,1,0,2,1,0,2};
__device__ __constant__ int BR_GNSEL[7]  = {0,1,0,2,1,0,2};
__device__ __constant__ int DWPFX[7]     = {0,6400,8000,9600,16000,16400,16800};
__device__ __constant__ int OMPFX[7]     = {0,6400,8000,9600,11200,11600,12000};
__device__ __constant__ int SAMP_PFX[7]  = {0,1600,2000,2400,2800,2900,3000};

// ---------------- scratch ----------------
__device__ float g_x0[NB*80*80*CH];
__device__ float g_x1[NB*40*40*CH];
__device__ float g_x2[NB*20*20*CH];
__device__ float g_dwb[18400*NB*CH];
__device__ float g_om [12400*NB*OMC];
__device__ float g_feat[12400*NB*CH];
__device__ float g_sum[8800*NB*CH];
__device__ float g_wT2[3*192*112];
__device__ float g_a[7*NB];
__device__ float g_y[3*NB*CH];
__device__ float g_z[3*NB*1024];
__device__ float g_cmean[7*NB*CH];
__device__ float g_gmu[7*NB*16];
__device__ float g_ginv[7*NB*16];

__device__ __forceinline__ const float* pick_x(int s){
    return s==0 ? g_x0 : (s==1 ? g_x1 : g_x2);
}
__device__ __forceinline__ float* pick_xm(int s){
    return s==0 ? g_x0 : (s==1 ? g_x1 : g_x2);
}

// ---------------- NCHW -> NHWC tiled transpose ----------------
__global__ void k_tr2(const float* __restrict__ in, int sel, int HW){
    __shared__ float tile[32][33];
    float* out = pick_xm(sel);
    int n  = blockIdx.z;
    int hw0 = blockIdx.x*32;
    int c0  = blockIdx.y*32;
    int tx = threadIdx.x, ty = threadIdx.y;
    #pragma unroll
    for (int q = 0; q < 4; ++q){
        int c = c0 + ty + q*8;
        int hw = hw0 + tx;
        float v = (hw < HW) ? in[((size_t)n*CH + c)*HW + hw] : 0.f;
        tile[ty + q*8][tx] = v;
    }
    __syncthreads();
    #pragma unroll
    for (int q = 0; q < 4; ++q){
        int hw = hw0 + ty + q*8;
        int c  = c0 + tx;
        if (hw < HW) out[((size_t)n*HW + hw)*CH + c] = tile[tx][ty + q*8];
    }
}

// weight transform: [dy][ic*3+dx][slot(4g x 28)]
__global__ void k_wt2(const float* __restrict__ ow){
    int i = blockIdx.x*blockDim.x + threadIdx.x;
    if (i >= 3*192*112) return;
    int slot = i % 112;
    int r    = (i / 112) % 192;
    int dy   = i / (112*192);
    int ic = r/3, dx = r%3;
    int g = slot/28, jj = slot%28;
    float v = 0.f;
    if (jj < 27) v = ow[(g*27+jj)*576 + ic*9 + dy*3 + dx];
    g_wT2[i] = v;
}

// ---------------- batched depthwise conv (all 7 branches), FFMA2 ----------------
__global__ void k_dwB(const float* __restrict__ wm, const float* __restrict__ sm_, const float* __restrict__ bm_,
                      const float* __restrict__ wh, const float* __restrict__ sh_, const float* __restrict__ bh_,
                      const float* __restrict__ wl, const float* __restrict__ sl_, const float* __restrict__ bl_){
    int b = blockIdx.y, n = blockIdx.z;
    int sel = BR_DWSEL[b];
    const float* wgt = sel==0 ? wm : (sel==1 ? wh : wl);
    const float* sc  = sel==0 ? sm_ : (sel==1 ? sh_ : sl_);
    const float* bi  = sel==0 ? bm_ : (sel==1 ? bh_ : bl_);
    const float* x = pick_x(BR_SRC[b]);
    int H = BR_HS[b], W = H, HW = H*W;
    float* dst = g_dwb + (size_t)DWPFX[b]*NB*CH;

    int q  = threadIdx.x & 63;
    int c0 = q*4;
    unsigned long long wr01[9], wr23[9];
    #pragma unroll
    for (int tp = 0; tp < 9; ++tp){
        float a0 = wgt[(c0+0)*9 + tp], a1 = wgt[(c0+1)*9 + tp];
        float a2 = wgt[(c0+2)*9 + tp], a3 = wgt[(c0+3)*9 + tp];
        PACKF2(wr01[tp], a0, a1);
        PACKF2(wr23[tp], a2, a3);
    }
    float4 s4 = *(const float4*)(sc + c0);
    float4 b4 = *(const float4*)(bi + c0);
    int lane = threadIdx.x >> 6;
    for (int hw = blockIdx.x*4 + lane; hw < HW; hw += gridDim.x*4){
        int w = hw % W, h = hw / W;
        unsigned long long a01 = 0ull, a23 = 0ull;
        #pragma unroll
        for (int dy = 0; dy < 3; ++dy){
            int yy = h + dy - 1;
            if (yy < 0 || yy >= H) continue;
            #pragma unroll
            for (int dx = 0; dx < 3; ++dx){
                int xx = w + dx - 1;
                if (xx < 0 || xx >= W) continue;
                ulonglong2 v = *(const ulonglong2*)(x + ((size_t)(n*H+yy)*W + xx)*CH + c0);
                int tp = dy*3 + dx;
                FMAF2(a01, v.x, wr01[tp], a01);
                FMAF2(a23, v.y, wr23[tp], a23);
            }
        }
        float ax, ay, az, aw;
        UNPACKF2(ax, ay, a01);
        UNPACKF2(az, aw, a23);
        float4 o;
        float t0 = ax*s4.x + b4.x; o.x = t0/(1.f+expf(-t0));
        float t1 = ay*s4.y + b4.y; o.y = t1/(1.f+expf(-t1));
        float t2 = az*s4.z + b4.z; o.z = t2/(1.f+expf(-t2));
        float t3 = aw*s4.w + b4.w; o.w = t3/(1.f+expf(-t3));
        *(float4*)(dst + ((size_t)n*HW + hw)*CH + c0) = o;
    }
}

// ---------------- grouped conv 256->108, per-group blocks, FFMA2 ----
template<int STRIDE, int PXO, int TPX, int PXQ, int THREADS>
__global__ void __launch_bounds__(THREADS)
k_om3(int H, int W, int Ho, int Wo, const float* __restrict__ ob, int bA, int bB){
    constexpr int PW  = (PXO-1)*STRIDE + 3;
    constexpr int PWP = (PW + 3) & ~3;
    constexpr int WIN = 3 + (TPX-1)*STRIDE;    // distinct window scalars per ic
    static_assert((TPX*STRIDE) % 4 == 0, "window alignment");
    static_assert(WIN <= 8, "window fits two float4");
    extern __shared__ float sh[];
    float* patch = sh;              // [64][PWP]
    float* wsl   = sh + 64*PWP;     // [192][28]

    int br   = blockIdx.z == 0 ? bA : bB;
    const float* src = g_dwb + (size_t)DWPFX[br]*NB*CH;
    float* dst       = g_om  + (size_t)OMPFX[br]*NB*OMC;

    int nt   = (Wo + PXO - 1)/PXO;
    int g    = blockIdx.y;
    int b    = blockIdx.x;
    int tile = b % nt;
    int ho   = (b/nt) % Ho;
    int n    = b/(nt*Ho);
    int wo0  = tile*PXO;
    int hsrc = ho*STRIDE;
    int wsrc0= wo0*STRIDE;
    int cb   = g*64;

    int t   = threadIdx.x;
    int pxq = t % PXQ;
    int li  = t / PXQ;
    bool act = li < 7;
    int xb  = pxq*TPX*STRIDE;

    unsigned long long a01[TPX], a23[TPX];
    #pragma unroll
    for (int p = 0; p < TPX; ++p){ a01[p] = 0ull; a23[p] = 0ull; }

    const float* wsrc_base = g_wT2 + g*28;
    for (int dy = 0; dy < 3; ++dy){
        __syncthreads();
        int gy = hsrc + dy - 1;
        for (int i = t; i < PW*64; i += THREADS){
            int c = i & 63, xx = i >> 6;
            int gx = wsrc0 + xx - 1;
            float v = 0.f;
            if (gy >= 0 && gy < H && gx >= 0 && gx < W)
                v = src[((size_t)(n*H+gy)*W + gx)*CH + cb + c];
            patch[c*PWP + xx] = v;
        }
        {
            const float* ws = wsrc_base + dy*192*112;
            for (int i = t; i < 192*7; i += THREADS){
                int row = i/7, col = (i%7)*4;
                *(float4*)(wsl + row*28 + col) = *(const float4*)(ws + row*112 + col);
            }
        }
        __syncthreads();
        if (act){
            #pragma unroll 4
            for (int ic = 0; ic < 64; ++ic){
                const float* pr = patch + ic*PWP + xb;
                float f[8];
                *(float4*)(f)   = *(const float4*)(pr);
                *(float4*)(f+4) = *(const float4*)(pr+4);
                unsigned long long sv[WIN];
                #pragma unroll
                for (int k2 = 0; k2 < WIN; ++k2) PACKF2(sv[k2], f[k2], f[k2]);
                const float* wb = wsl + (ic*3)*28 + li*4;
                #pragma unroll
                for (int dx = 0; dx < 3; ++dx){
                    ulonglong2 wv = *(const ulonglong2*)(wb + dx*28);
                    #pragma unroll
                    for (int p = 0; p < TPX; ++p){
                        FMAF2(a01[p], sv[dx + p*STRIDE], wv.x, a01[p]);
                        FMAF2(a23[p], sv[dx + p*STRIDE], wv.y, a23[p]);
                    }
                }
            }
        }
    }
    if (act){
        float bj[4];
        #pragma unroll
        for (int j = 0; j < 4; ++j){
            int jj = li*4 + j;
            bj[j] = (jj < 27) ? ob[g*27 + jj] : 0.f;
        }
        #pragma unroll
        for (int p = 0; p < TPX; ++p){
            int wo = wo0 + pxq*TPX + p;
            if (wo < Wo){
                size_t base = ((size_t)(n*Ho+ho)*Wo + wo)*OMC + g*27 + li*4;
                float av[4];
                UNPACKF2(av[0], av[1], a01[p]);
                UNPACKF2(av[2], av[3], a23[p]);
                #pragma unroll
                for (int j = 0; j < 4; ++j)
                    if (li*4 + j < 27) dst[base + j] = av[j] + bj[j];
            }
        }
    }
}

// ---------------- batched DCNv3 sampler, FFMA2 gather ----------------
__global__ void k_sampB(){
    __shared__ float som[4][OMC];
    __shared__ float smk[4][36];
    __shared__ float sw[4][4][9][4];
    __shared__ int   soff[4][4][9][4];
    int bx = blockIdx.x;
    int b = 0;
    #pragma unroll
    for (int i = 1; i < 7; ++i) if (bx >= SAMP_PFX[i]) b = i;
    int n = blockIdx.y;
    int p0 = (bx - SAMP_PFX[b])*4;
    int Ho = BR_HO[b], Wo = Ho, HW = Ho*Wo;
    int H  = BR_HS[b], W = H;
    int stride = BR_STRIDE[b];
    int use_softmax = BR_SOFT[b];
    const float* x = pick_x(BR_SRC[b]);
    const float* omp = g_om + ((size_t)OMPFX[b]*NB + (size_t)n*HW)*OMC;
    int t = threadIdx.x;

    for (int i = t; i < 4*OMC; i += 256)
        som[i/OMC][i%OMC] = omp[(size_t)(p0 + i/OMC)*OMC + i%OMC];
    __syncthreads();

    if (use_softmax){
        if (t < 16){
            int pp = t >> 2, gg = t & 3;
            float mx = -1e30f;
            #pragma unroll
            for (int k = 0; k < 9; ++k) mx = fmaxf(mx, som[pp][72 + gg*9 + k]);
            float e[9], s = 0.f;
            #pragma unroll
            for (int k = 0; k < 9; ++k){ e[k] = expf(som[pp][72 + gg*9 + k] - mx); s += e[k]; }
            float inv = 1.f/s;
            #pragma unroll
            for (int k = 0; k < 9; ++k) smk[pp][gg*9 + k] = e[k]*inv;
        }
    } else {
        for (int i = t; i < 4*36; i += 256)
            smk[i/36][i%36] = 1.f/(1.f + expf(-som[i/36][72 + i%36]));
    }
    __syncthreads();

    if (t < 144){
        int pix = t / 36, r = t % 36, gg = r / 9, k = r % 9;
        int hw = p0 + pix;
        int wo = hw % Wo, ho = hw / Wo;
        float py = (float)(ho*stride) + (float)(k/3 - 1) + som[pix][gg*18 + k*2];
        float px = (float)(wo*stride) + (float)(k%3 - 1) + som[pix][gg*18 + k*2 + 1];
        float m  = smk[pix][gg*9 + k];
        float fy = floorf(py), fx = floorf(px);
        float wy = py - fy, wx = px - fx;
        int iy = (int)fy, ix = (int)fx;
        #pragma unroll
        for (int d0 = 0; d0 < 2; ++d0){
            int yy = iy + d0;
            float wgy = d0 ? wy : (1.f - wy);
            #pragma unroll
            for (int d1 = 0; d1 < 2; ++d1){
                int xx = ix + d1;
                bool valid = (yy >= 0) & (yy < H) & (xx >= 0) & (xx < W);
                int yc = min(max(yy, 0), H-1);
                int xc = min(max(xx, 0), W-1);
                sw[pix][gg][k][d0*2+d1]   = valid ? wgy*(d1 ? wx : (1.f - wx))*m : 0.f;
                soff[pix][gg][k][d0*2+d1] = ((n*H + yc)*W + xc)*CH;
            }
        }
    }
    __syncthreads();

    int pix = t >> 6, q = t & 63, c0 = q*4, g = q >> 4;
    const float* xc = x + c0;
    unsigned long long acc01 = 0ull, acc23 = 0ull;
    #pragma unroll
    for (int k = 0; k < 9; ++k){
        float4 wv = *(const float4*)&sw[pix][g][k][0];
        int4  ov = *(const int4*)&soff[pix][g][k][0];
        unsigned long long w0, w1, w2, w3;
        PACKF2(w0, wv.x, wv.x); PACKF2(w1, wv.y, wv.y);
        PACKF2(w2, wv.z, wv.z); PACKF2(w3, wv.w, wv.w);
        ulonglong2 v0 = *(const ulonglong2*)(xc + ov.x);
        ulonglong2 v1 = *(const ulonglong2*)(xc + ov.y);
        ulonglong2 v2 = *(const ulonglong2*)(xc + ov.z);
        ulonglong2 v3 = *(const ulonglong2*)(xc + ov.w);
        FMAF2(acc01, v0.x, w0, acc01); FMAF2(acc23, v0.y, w0, acc23);
        FMAF2(acc01, v1.x, w1, acc01); FMAF2(acc23, v1.y, w1, acc23);
        FMAF2(acc01, v2.x, w2, acc01); FMAF2(acc23, v2.y, w2, acc23);
        FMAF2(acc01, v3.x, w3, acc01); FMAF2(acc23, v3.y, w3, acc23);
    }
    float4 acc;
    UNPACKF2(acc.x, acc.y, acc01);
    UNPACKF2(acc.z, acc.w, acc23);
    *(float4*)(g_feat + ((size_t)OMPFX[b]*NB + (size_t)n*HW + p0 + pix)*CH + c0) = acc;
}

// ---------------- batched stats: GN mean/var + weighted channel means --------
__global__ void k_statsB(){
    __shared__ float wy[80], wx[80];
    __shared__ float r1[256], r2[256];
    __shared__ float4 rw[256];
    int b = blockIdx.x >> 4, g = blockIdx.x & 15, n = blockIdx.y;
    int Hs = BR_HO[b], Ws = Hs, HW = Hs*Ws;
    int uph = BR_UPH[b];
    float normw = uph ? 1.f/((float)uph*(float)uph) : 1.f/(float)HW;
    int t = threadIdx.x;
    if (t == 0){
        if (uph){
            for (int i = 0; i < Hs; ++i){ wy[i] = 0.f; wx[i] = 0.f; }
            float ry = (float)(Hs-1)/(float)(uph-1);
            for (int j = 0; j < uph; ++j){
                float c = j*ry; int i0 = (int)floorf(c); float f = c - (float)i0;
                wy[i0] += 1.f - f;
                if (i0 + 1 < Hs) wy[i0+1] += f;
            }
            for (int i = 0; i < Hs; ++i) wx[i] = wy[i];
        } else {
            for (int i = 0; i < Hs; ++i){ wy[i] = 1.f; wx[i] = 1.f; }
        }
    }
    __syncthreads();

    const float* fb = g_feat + ((size_t)OMPFX[b]*NB + (size_t)n*HW)*CH;
    int q  = t & 3;
    int c0 = g*16 + q*4;
    float4 s4 = make_float4(0,0,0,0), w4 = make_float4(0,0,0,0);
    float ss = 0.f;
    int hw0 = t >> 2;
    int h = hw0 / Ws, w = hw0 % Ws;
    for (int hw = hw0; hw < HW; hw += 64){
        float4 v = *(const float4*)(fb + (size_t)hw*CH + c0);
        s4.x += v.x; s4.y += v.y; s4.z += v.z; s4.w += v.w;
        ss += v.x*v.x + v.y*v.y + v.z*v.z + v.w*v.w;
        float ww = wy[h]*wx[w];
        w4.x += v.x*ww; w4.y += v.y*ww; w4.z += v.z*ww; w4.w += v.w*ww;
        w += 64; while (w >= Ws){ w -= Ws; ++h; }
    }
    r1[t] = s4.x + s4.y + s4.z + s4.w;
    r2[t] = ss;
    rw[t] = w4;
    __syncthreads();
    for (int o = 128; o >= 4; o >>= 1){
        if (t < o){
            r1[t] += r1[t+o]; r2[t] += r2[t+o];
            rw[t].x += rw[t+o].x; rw[t].y += rw[t+o].y;
            rw[t].z += rw[t+o].z; rw[t].w += rw[t+o].w;
        }
        __syncthreads();
    }
    if (t == 0){
        float s  = r1[0] + r1[1] + r1[2] + r1[3];
        float sq = r2[0] + r2[1] + r2[2] + r2[3];
        float cnt = (float)HW*16.f;
        float mu  = s/cnt;
        float var = sq/cnt - mu*mu;
        g_gmu [(b*NB+n)*16 + g] = mu;
        g_ginv[(b*NB+n)*16 + g] = rsqrtf(var + 1e-5f);
    }
    if (t < 4){
        float4 wv = rw[t];
        int c = (b*NB+n)*CH + g*16 + t*4;
        g_cmean[c]   = wv.x*normw; g_cmean[c+1] = wv.y*normw;
        g_cmean[c+2] = wv.z*normw; g_cmean[c+3] = wv.w*normw;
    }
}

// ---------------- attn scalars + pooled means, all levels ----------------
__device__ __constant__ int LVL_NBR[3] = {2,3,2};
__device__ __constant__ int LVL_BRS[3][3] = {{0,1,-1},{2,3,4},{5,6,-1}};

__global__ void k_attnB(const float* __restrict__ saw, const float* __restrict__ sab,
                        const float* __restrict__ gm, const float* __restrict__ bm,
                        const float* __restrict__ gh, const float* __restrict__ bh,
                        const float* __restrict__ gl, const float* __restrict__ bl){
    __shared__ float red[256];
    __shared__ float sa;
    int lvl = blockIdx.x, n = blockIdx.y, t = threadIdx.x;
    int g = t >> 4;
    int nbr = LVL_NBR[lvl];
    float invl = 1.f/(float)nbr;
    float y = 0.f;
    for (int i = 0; i < nbr; ++i){
        int b = LVL_BRS[lvl][i];
        int gs = BR_GNSEL[b];
        const float* gam = gs==0 ? gm : (gs==1 ? gh : gl);
        const float* bet = gs==0 ? bm : (gs==1 ? bh : bl);
        float m = (g_cmean[(b*NB+n)*CH + t] - g_gmu[(b*NB+n)*16 + g])
                  * g_ginv[(b*NB+n)*16 + g] * gam[t] + bet[t];
        red[t] = m*saw[t];
        __syncthreads();
        for (int o = 128; o > 0; o >>= 1){
            if (t < o) red[t] += red[t+o];
            __syncthreads();
        }
        if (t == 0){
            float a = red[0] + sab[0];
            a = fmaxf(a, 0.f);
            a = fminf(fmaxf((a + 3.f)/6.f, 0.f), 1.f);
            sa = a; g_a[b*NB + n] = a;
        }
        __syncthreads();
        y += sa*m*invl;
        __syncthreads();
    }
    g_y[(lvl*NB + n)*CH + t] = y;
}

// ---------------- per-level fused accumulate (GN + attn + upsample + sum) ----
__device__ __forceinline__ float4 feat_rd(int b, int n, int HW, int hw, int c0){
    return *(const float4*)(g_feat + ((size_t)OMPFX[b]*NB + (size_t)n*HW + hw)*CH + c0);
}
__device__ __forceinline__ float4 feat_up(int b, int n, int Hs, int Ho, int h, int w, int c0){
    float r = (float)(Hs-1)/(float)(Ho-1);
    float cy = h*r, cx = w*r;
    int y0 = (int)floorf(cy), x0 = (int)floorf(cx);
    int y1 = min(y0+1, Hs-1), x1 = min(x0+1, Hs-1);
    float wyf = cy - (float)y0, wxf = cx - (float)x0;
    const float* fb = g_feat + ((size_t)OMPFX[b]*NB + (size_t)n*Hs*Hs)*CH + c0;
    float4 v00 = *(const float4*)(fb + (size_t)(y0*Hs + x0)*CH);
    float4 v01 = *(const float4*)(fb + (size_t)(y0*Hs + x1)*CH);
    float4 v10 = *(const float4*)(fb + (size_t)(y1*Hs + x0)*CH);
    float4 v11 = *(const float4*)(fb + (size_t)(y1*Hs + x1)*CH);
    float a0 = (1.f-wyf)*(1.f-wxf), a1 = (1.f-wyf)*wxf, a2 = wyf*(1.f-wxf), a3 = wyf*wxf;
    float4 o;
    o.x = v00.x*a0 + v01.x*a1 + v10.x*a2 + v11.x*a3;
    o.y = v00.y*a0 + v01.y*a1 + v10.y*a2 + v11.y*a3;
    o.z = v00.z*a0 + v01.z*a1 + v10.z*a2 + v11.z*a3;
    o.w = v00.w*a0 + v01.w*a1 + v10.w*a2 + v11.w*a3;
    return o;
}
__device__ __forceinline__ void gn_acc(float4& o, float4 raw, int b, int n, int g, int c0,
                                       const float* gam, const float* bet){
    float mu = g_gmu[(b*NB+n)*16 + g], inv = g_ginv[(b*NB+n)*16 + g], a = g_a[b*NB + n];
    float4 g4 = *(const float4*)(gam + c0);
    float4 b4 = *(const float4*)(bet + c0);
    o.x += a*((raw.x - mu)*inv*g4.x + b4.x);
    o.y += a*((raw.y - mu)*inv*g4.y + b4.y);
    o.z += a*((raw.z - mu)*inv*g4.z + b4.z);
    o.w += a*((raw.w - mu)*inv*g4.w + b4.w);
}

template<int LVL>
__global__ void k_accL(const float* __restrict__ gm, const float* __restrict__ bm,
                       const float* __restrict__ gh, const float* __restrict__ bh,
                       const float* __restrict__ gl, const float* __restrict__ bl){
    constexpr int HoL = (LVL==0) ? 80 : (LVL==1 ? 40 : 20);
    constexpr int HWL = HoL*HoL;
    constexpr int SUMP = (LVL==0) ? 0 : (LVL==1 ? 6400 : 8000);
    int n = blockIdx.y;
    int idx = blockIdx.x*256 + threadIdx.x;
    if (idx >= HWL*64) return;
    int q = idx & 63, hw = idx >> 6;
    int c0 = q*4, g = q >> 2;
    int w = hw % HoL, h = hw / HoL;
    float4 o = make_float4(0,0,0,0);
    if (LVL == 0){
        gn_acc(o, feat_rd(0, n, 6400, hw, c0), 0, n, g, c0, gm, bm);
        gn_acc(o, feat_up(1, n, 40, 80, h, w, c0), 1, n, g, c0, gh, bh);
    } else if (LVL == 1){
        gn_acc(o, feat_rd(2, n, 1600, hw, c0), 2, n, g, c0, gm, bm);
        gn_acc(o, feat_rd(3, n, 1600, hw, c0), 3, n, g, c0, gl, bl);
        gn_acc(o, feat_up(4, n, 20, 40, h, w, c0), 4, n, g, c0, gh, bh);
    } else {
        gn_acc(o, feat_rd(5, n, 400, hw, c0), 5, n, g, c0, gm, bm);
        gn_acc(o, feat_rd(6, n, 400, hw, c0), 6, n, g, c0, gl, bl);
    }
    *(float4*)(g_sum + ((size_t)SUMP*NB + (size_t)n*HWL + hw)*CH + c0) = o;
}

// ---------------- fc (all levels) ----------------
__global__ void k_fcB(const float* __restrict__ w1, const float* __restrict__ b1,
                      const float* __restrict__ w2, const float* __restrict__ b2){
    __shared__ float h[4][64];
    int lvl = blockIdx.x;
    int t = threadIdx.x;
    int n = t >> 6, j = t & 63;
    float s = b1[j];
    const float* wr = w1 + j*CH;
    const float* yv = g_y + (lvl*NB + n)*CH;
    for (int c = 0; c < CH; ++c) s += yv[c]*wr[c];
    h[n][j] = fmaxf(s, 0.f);
    __syncthreads();
    for (int og = t; og < NB*1024; og += 256){
        int nn = og >> 10, o = og & 1023;
        float s2 = b2[o];
        const float* w2r = w2 + o*64;
        #pragma unroll 16
        for (int j2 = 0; j2 < 64; ++j2) s2 += h[nn][j2]*w2r[j2];
        float z = fminf(fmaxf(s2 + 3.f, 0.f), 6.f)*(1.f/6.f);
        int qd = o >> 8;
        float v;
        if      (qd == 0) v = (z - 0.5f)*2.f + 1.f;
        else if (qd == 2) v = (z - 0.5f)*2.f;
        else              v = z - 0.5f;
        g_z[(lvl*NB + nn)*1024 + o] = v;
    }
}

// ---------------- dyrelu + NHWC->NCHW output ----------------
__global__ void k_out2(int HW, float invl, float* __restrict__ out, int sump, int lvl){
    __shared__ float tile[32][33];
    int n   = blockIdx.z;
    int hw0 = blockIdx.x*32;
    int c0  = blockIdx.y*32;
    int tx = threadIdx.x, ty = threadIdx.y;
    const float* sb = g_sum + ((size_t)sump*NB + (size_t)n*HW)*CH;
    #pragma unroll
    for (int q = 0; q < 4; ++q){
        int hw = hw0 + ty + q*8;
        float v = (hw < HW) ? sb[(size_t)hw*CH + c0 + tx] : 0.f;
        tile[ty + q*8][tx] = v;
    }
    __syncthreads();
    int hw = hw0 + tx;
    if (hw < HW){
        const float* zb = g_z + (lvl*NB + n)*1024;
        #pragma unroll
        for (int q = 0; q < 4; ++q){
            int cl = ty + q*8;
            int c  = c0 + cl;
            float f  = tile[tx][cl]*invl;
            float a1 = zb[c];
            float b1 = zb[256 + c];
            float a2 = zb[512 + c];
            float b2 = zb[768 + c];
            out[((size_t)n*CH + c)*HW + hw] = fmaxf(f*a1 + b1, f*a2 + b2);
        }
    }
}

// ---------------- host ----------------
extern "C" void kernel_launch(void* const* d_in, const int* in_sizes, int n_in,
                              void* d_out, int out_size){
    const float* x0     = (const float*)d_in[0];
    const float* x1     = (const float*)d_in[1];
    const float* x2     = (const float*)d_in[2];
    const float* dw_w_h = (const float*)d_in[3];
    const float* dw_s_h = (const float*)d_in[4];
    const float* dw_b_h = (const float*)d_in[5];
    const float* dw_w_m = (const float*)d_in[6];
    const float* dw_s_m = (const float*)d_in[7];
    const float* dw_b_m = (const float*)d_in[8];
    const float* dw_w_l = (const float*)d_in[9];
    const float* dw_s_l = (const float*)d_in[10];
    const float* dw_b_l = (const float*)d_in[11];
    const float* off_w  = (const float*)d_in[12];
    const float* off_b  = (const float*)d_in[13];
    const float* gn_g_h = (const float*)d_in[14];
    const float* gn_b_h = (const float*)d_in[15];
    const float* gn_g_m = (const float*)d_in[16];
    const float* gn_b_m = (const float*)d_in[17];
    const float* gn_g_l = (const float*)d_in[18];
    const float* gn_b_l = (const float*)d_in[19];
    const float* sa_w   = (const float*)d_in[20];
    const float* sa_b   = (const float*)d_in[21];
    const float* fc1_w  = (const float*)d_in[22];
    const float* fc1_b  = (const float*)d_in[23];
    const float* fc2_w  = (const float*)d_in[24];
    const float* fc2_b  = (const float*)d_in[25];
    float* out = (float*)d_out;

    // stage 1: layout transforms, then batched dw (#3 <- ncu)
    k_tr2<<<dim3(200, 8, NB), dim3(32,8)>>>(x0, 0, 6400);
    k_tr2<<<dim3(50,  8, NB), dim3(32,8)>>>(x1, 1, 1600);
    k_tr2<<<dim3(13,  8, NB), dim3(32,8)>>>(x2, 2,  400);
    k_dwB<<<dim3(200, 7, NB), 256>>>(dw_w_m, dw_s_m, dw_b_m,
                                     dw_w_h, dw_s_h, dw_b_h,
                                     dw_w_l, dw_s_l, dw_b_l);
    k_wt2<<<(3*192*112 + 255)/256, 256>>>(off_w);

    // stage 2: offset/mask convs (5 launches, shape-classed)
    {
        const int SM80 = (64*52 + 192*28)*4;
        k_om3<1,48,4,12,96><<<dim3(2*80*NB, 4, 1), 96, SM80>>>(80, 80, 80, 80, off_b, 0, 0);
        const int SM40 = (64*44 + 192*28)*4;
        k_om3<1,40,4,10,80><<<dim3(1*40*NB, 4, 2), 80, SM40>>>(40, 40, 40, 40, off_b, 1, 2);
        k_om3<2,20,2,10,80><<<dim3(2*40*NB, 4, 1), 80, SM40>>>(80, 80, 40, 40, off_b, 3, 3);
        const int SM20 = (64*24 + 192*28)*4;
        k_om3<1,20,4,5,64><<<dim3(1*20*NB, 4, 2), 64, SM20>>>(20, 20, 20, 20, off_b, 4, 5);
        k_om3<2,20,2,10,80><<<dim3(1*20*NB, 4, 1), 80, SM40>>>(40, 40, 20, 20, off_b, 6, 6);
    }

    // stage 3: sampling, stats, attn
    k_sampB<<<dim3(3100, NB), 256>>>();
    k_statsB<<<dim3(7*16, NB), 256>>>();
    k_attnB<<<dim3(3, NB), 256>>>(sa_w, sa_b, gn_g_m, gn_b_m, gn_g_h, gn_b_h, gn_g_l, gn_b_l);

    // stage 4: fused per-level accumulate, fc, output
    k_accL<0><<<dim3(6400*64/256, NB), 256>>>(gn_g_m, gn_b_m, gn_g_h, gn_b_h, gn_g_l, gn_b_l);
    k_accL<1><<<dim3(1600*64/256, NB), 256>>>(gn_g_m, gn_b_m, gn_g_h, gn_b_h, gn_g_l, gn_b_l);
    k_accL<2><<<dim3( 400*64/256, NB), 256>>>(gn_g_m, gn_b_m, gn_g_h, gn_b_h, gn_g_l, gn_b_l);
    k_fcB<<<3, 256>>>(fc1_w, fc1_b, fc2_w, fc2_b);

    k_out2<<<dim3(200, 8, NB), dim3(32,8)>>>(6400, 0.5f,     out,                                           0,    0);
    k_out2<<<dim3(50,  8, NB), dim3(32,8)>>>(1600, 1.f/3.f,  out + (size_t)NB*CH*6400,                      6400, 1);
    k_out2<<<dim3(13,  8, NB), dim3(32,8)>>>(400,  0.5f,     out + (size_t)NB*CH*6400 + (size_t)NB*CH*1600, 8000, 2);
}